// round 1
// baseline (speedup 1.0000x reference)
#include <cuda_runtime.h>
#include <math.h>

#define Bb 2
#define Cc 128
#define Hh 128
#define WW 128
#define HW 16384        // Hh*Ww
#define Nn 32768        // Bb*HW
#define Ee 6
#define HFf 512
#define EPS_LOGF 2.220446049250313e-16f

// ---------------- scratch (device globals; no allocation allowed) -------------
__device__ float         g_xf[Nn * Cc];          // 16 MB token-major activations
__device__ float         g_gate[Nn * 2];         // g0,g1 per token
__device__ unsigned char g_eidx[Nn * 2];         // expert ids per token
__device__ int           g_cnt[Ee];
__device__ int           g_off[Ee + 1];
__device__ int           g_cur[Ee];
__device__ unsigned int  g_list[Nn * 2];         // entries: n*2+slot, grouped by expert
__device__ float         g_outbuf[(size_t)Nn * 2 * Cc]; // 32 MB raw expert outputs per slot
__device__ float         g_bias[Bb * Ee];

// ---------------- k0: per-batch gate bias + zero counters ---------------------
__global__ void k0_bias(const float* __restrict__ prompt,
                        const float* __restrict__ de_cls,
                        const float* __restrict__ w_g,
                        const float* __restrict__ gate_boost,
                        const float* __restrict__ degra_w,
                        const float* __restrict__ degra_b) {
    int tid = threadIdx.x;
    if (tid < Ee) g_cnt[tid] = 0;
    if (tid < Bb * Ee) {
        int b = tid / Ee, e = tid % Ee;
        float acc = 0.f;
        for (int c = 0; c < Cc; c++)
            acc += prompt[b * Cc + c] * w_g[(Cc + c) * Ee + e];
        float db = 0.f;
        for (int d = 0; d < Ee; d++)
            db += de_cls[b * Ee + d] * degra_w[d * Ee + e];
        g_bias[b * Ee + e] = acc + gate_boost[0] * (db + degra_b[e]);
    }
}

// ---------------- k1: transpose x -> xf + gating ------------------------------
// block = 64 tokens, 256 threads
__global__ __launch_bounds__(256) void k1_gate(const float* __restrict__ x,
                                               const float* __restrict__ w_g) {
    __shared__ float s[Cc * 65];      // [c][t] pad 65
    __shared__ float wg_s[Cc * Ee];   // first half of w_g

    int tid = threadIdx.x;
    int n0 = blockIdx.x * 64;
    int batch = n0 >> 14;
    int hw0 = n0 & (HW - 1);

    for (int i = tid; i < Cc * Ee; i += 256) wg_s[i] = w_g[i];

    // load x tile coalesced: [c][t]
    for (int idx = tid; idx < Cc * 64; idx += 256) {
        int c = idx >> 6, t = idx & 63;
        s[c * 65 + t] = x[((size_t)(batch * Cc + c)) * HW + hw0 + t];
    }
    __syncthreads();

    // write xf rows coalesced
    for (int idx = tid; idx < 64 * Cc; idx += 256) {
        int t = idx >> 7, c = idx & 127;
        g_xf[(size_t)(n0 + t) * Cc + c] = s[c * 65 + t];
    }

    // gating: one thread per token (threads < 64)
    if (tid < 64) {
        int n = n0 + tid;
        float acc[Ee];
        #pragma unroll
        for (int e = 0; e < Ee; e++) acc[e] = g_bias[batch * Ee + e];
        for (int c = 0; c < Cc; c++) {
            float xv = s[c * 65 + tid];
            #pragma unroll
            for (int e = 0; e < Ee; e++) acc[e] += xv * wg_s[c * Ee + e];
        }
        // top-2, lowest index on ties (strict >)
        float v0 = -3.4e38f; int i0 = 0;
        #pragma unroll
        for (int e = 0; e < Ee; e++) if (acc[e] > v0) { v0 = acc[e]; i0 = e; }
        float v1 = -3.4e38f; int i1 = 0;
        #pragma unroll
        for (int e = 0; e < Ee; e++) if (e != i0 && acc[e] > v1) { v1 = acc[e]; i1 = e; }
        float t = expf(v1 - v0);
        float inv = 1.f / (1.f + t);
        float g0c = inv, g1c = t * inv;
        g_eidx[n * 2 + 0] = (unsigned char)i0;
        g_eidx[n * 2 + 1] = (unsigned char)i1;
        g_gate[n * 2 + 0] = g0c;
        g_gate[n * 2 + 1] = g1c;
        atomicAdd(&g_cnt[i0], 1);
        atomicAdd(&g_cnt[i1], 1);
    }
}

// ---------------- k2: deterministic loss + list offsets -----------------------
__global__ __launch_bounds__(256) void k2_loss(float* __restrict__ d_out, int out_size) {
    __shared__ double red[256 * Ee];
    int tid = threadIdx.x;
    double wp[Ee];
    #pragma unroll
    for (int e = 0; e < Ee; e++) wp[e] = 0.0;
    for (int n = tid; n < Nn; n += 256) {
        #pragma unroll
        for (int s = 0; s < 2; s++) {
            int e = g_eidx[n * 2 + s];
            wp[e] += (double)g_gate[n * 2 + s];
        }
    }
    #pragma unroll
    for (int e = 0; e < Ee; e++) red[tid * Ee + e] = wp[e];
    __syncthreads();
    for (int sft = 128; sft > 0; sft >>= 1) {
        if (tid < sft) {
            #pragma unroll
            for (int e = 0; e < Ee; e++)
                red[tid * Ee + e] += red[(tid + sft) * Ee + e];
        }
        __syncthreads();
    }
    if (tid == 0) {
        // offsets / cursors
        int off = 0;
        for (int e = 0; e < Ee; e++) {
            g_off[e] = off; g_cur[e] = off; off += g_cnt[e];
        }
        g_off[Ee] = off;
        // balance(Weight) + balance(counts)
        double W[Ee], S[Ee];
        for (int e = 0; e < Ee; e++) { W[e] = red[e]; S[e] = (double)g_cnt[e]; }
        double mW = 0, mS = 0;
        for (int e = 0; e < Ee; e++) { mW += W[e]; mS += S[e]; }
        mW /= Ee; mS /= Ee;
        double vW = 0, vS = 0;
        for (int e = 0; e < Ee; e++) {
            vW += (W[e] - mW) * (W[e] - mW);
            vS += (S[e] - mS) * (S[e] - mS);
        }
        vW /= (Ee - 1); vS /= (Ee - 1);
        double loss = vW / (mW * mW + 1e-10) + vS / (mS * mS + 1e-10);
        if (out_size > Nn * Cc) d_out[Nn * Cc] = (float)loss;
    }
}

// ---------------- k3: scatter tokens into per-expert lists --------------------
__global__ __launch_bounds__(256) void k3_scatter() {
    int n = blockIdx.x * 256 + threadIdx.x;
    if (n >= Nn) return;
    #pragma unroll
    for (int s = 0; s < 2; s++) {
        int e = g_eidx[n * 2 + s];
        int pos = atomicAdd(&g_cur[e], 1);
        g_list[pos] = (unsigned int)(n * 2 + s);
    }
}

// ---------------- k4: fused per-expert MLP (the hot kernel) -------------------
// tile = 64 tokens x one expert; 256 threads; thread tile 4m x 8n.
// dyn smem: As[128][68] + As2[128][68] + Bs[32*128]
#define AS_STRIDE 68
#define K4_SMEM_FLOATS (2 * 128 * AS_STRIDE + 32 * 128)
#define K4_GRID 1030

__global__ __launch_bounds__(256, 2) void k4_mlp(const float* __restrict__ fc1_w,
                                                 const float* __restrict__ fc1_b,
                                                 const float* __restrict__ fc2_w,
                                                 const float* __restrict__ fc2_b) {
    extern __shared__ float sm[];
    float* As  = sm;                         // [k=128][m=64] pad 68
    float* As2 = sm + 128 * AS_STRIDE;       // gelu(hid) chunk, same layout
    float* Bs  = sm + 2 * 128 * AS_STRIDE;   // [32][128] weight chunk

    __shared__ int stoks[64];
    __shared__ int s_meta[3];

    int tid = threadIdx.x;
    if (tid == 0) {
        int rem = blockIdx.x;
        int e = 0, found = 0;
        for (; e < Ee; e++) {
            int t = (g_cnt[e] + 63) >> 6;
            if (rem < t) { found = 1; break; }
            rem -= t;
        }
        if (!found) { s_meta[0] = -1; }
        else {
            s_meta[0] = e;
            s_meta[1] = g_off[e] + rem * 64;
            int mc = g_cnt[e] - rem * 64;
            s_meta[2] = mc < 64 ? mc : 64;
        }
    }
    __syncthreads();
    int e = s_meta[0];
    if (e < 0) return;
    int base = s_meta[1], mcount = s_meta[2];

    if (tid < 64) {
        int i = tid < mcount ? tid : (mcount - 1);
        stoks[tid] = (int)g_list[base + i];
    }
    __syncthreads();

    // load A (gathered xf rows) into As[k][m]
    for (int idx = tid; idx < 64 * 128; idx += 256) {
        int m = idx >> 7, c = idx & 127;
        int n = stoks[m] >> 1;
        As[c * AS_STRIDE + m] = g_xf[(size_t)n * Cc + c];
    }

    int tx = tid & 15, ty = tid >> 4;
    int n0 = tx * 8, m0 = ty * 4;

    const float* W1 = fc1_w + (size_t)e * Cc * HFf;
    const float* W2 = fc2_w + (size_t)e * HFf * Cc;

    float out_acc[4][8];
    #pragma unroll
    for (int i = 0; i < 4; i++)
        #pragma unroll
        for (int j = 0; j < 8; j++) out_acc[i][j] = 0.f;

    for (int hc = 0; hc < 4; hc++) {
        int hbase = hc * 128;
        float acc[4][8];
        #pragma unroll
        for (int i = 0; i < 4; i++)
            #pragma unroll
            for (int j = 0; j < 8; j++) acc[i][j] = 0.f;

        // ---- GEMM1: xf[64x128] @ W1[:, hbase:hbase+128] ----
        for (int ks = 0; ks < 4; ks++) {
            __syncthreads();
            for (int idx = tid; idx < 32 * 128; idx += 256) {
                int kk = idx >> 7, nn = idx & 127;
                Bs[idx] = W1[(size_t)(ks * 32 + kk) * HFf + hbase + nn];
            }
            __syncthreads();
            #pragma unroll
            for (int kk = 0; kk < 32; kk++) {
                int k = ks * 32 + kk;
                float4 a  = *(const float4*)&As[k * AS_STRIDE + m0];
                float4 b0 = *(const float4*)&Bs[kk * 128 + n0];
                float4 b1 = *(const float4*)&Bs[kk * 128 + n0 + 4];
                float av[4] = {a.x, a.y, a.z, a.w};
                float bv[8] = {b0.x, b0.y, b0.z, b0.w, b1.x, b1.y, b1.z, b1.w};
                #pragma unroll
                for (int i = 0; i < 4; i++)
                    #pragma unroll
                    for (int j = 0; j < 8; j++)
                        acc[i][j] = fmaf(av[i], bv[j], acc[i][j]);
            }
        }
        // bias + exact GELU -> As2[h_local][m]
        #pragma unroll
        for (int j = 0; j < 8; j++) {
            float bias = fc1_b[e * HFf + hbase + n0 + j];
            #pragma unroll
            for (int i = 0; i < 4; i++) {
                float v = acc[i][j] + bias;
                v = 0.5f * v * (1.0f + erff(v * 0.7071067811865476f));
                As2[(n0 + j) * AS_STRIDE + (m0 + i)] = v;
            }
        }
        // ---- GEMM2: gelu(hid)[64x128chunk] @ W2[hbase:hbase+128, :] ----
        for (int ks = 0; ks < 4; ks++) {
            __syncthreads();
            for (int idx = tid; idx < 32 * 128; idx += 256) {
                int kk = idx >> 7, nn = idx & 127;
                Bs[idx] = W2[(size_t)(hbase + ks * 32 + kk) * Cc + nn];
            }
            __syncthreads();
            #pragma unroll
            for (int kk = 0; kk < 32; kk++) {
                int k = ks * 32 + kk;
                float4 a  = *(const float4*)&As2[k * AS_STRIDE + m0];
                float4 b0 = *(const float4*)&Bs[kk * 128 + n0];
                float4 b1 = *(const float4*)&Bs[kk * 128 + n0 + 4];
                float av[4] = {a.x, a.y, a.z, a.w};
                float bv[8] = {b0.x, b0.y, b0.z, b0.w, b1.x, b1.y, b1.z, b1.w};
                #pragma unroll
                for (int i = 0; i < 4; i++)
                    #pragma unroll
                    for (int j = 0; j < 8; j++)
                        out_acc[i][j] = fmaf(av[i], bv[j], out_acc[i][j]);
            }
        }
    }

    // epilogue: + fc2_b, write raw out rows per (token,slot)
    #pragma unroll
    for (int i = 0; i < 4; i++) {
        int m = m0 + i;
        if (m < mcount) {
            int entry = stoks[m];
            float* orow = g_outbuf + (size_t)entry * Cc + n0;
            #pragma unroll
            for (int j = 0; j < 8; j++)
                orow[j] = out_acc[i][j] + fc2_b[e * Cc + n0 + j];
        }
    }
}

// ---------------- k5: combine (log-sum of gated exps) + transpose out ---------
__global__ __launch_bounds__(256) void k5_combine(float* __restrict__ d_out) {
    __shared__ float s[Cc * 65];
    int tid = threadIdx.x;
    int n0 = blockIdx.x * 64;
    int batch = n0 >> 14;
    int hw0 = n0 & (HW - 1);

    for (int idx = tid; idx < 64 * Cc; idx += 256) {
        int t = idx >> 7, c = idx & 127;
        int n = n0 + t;
        float o0 = g_outbuf[(size_t)(n * 2 + 0) * Cc + c];
        float o1 = g_outbuf[(size_t)(n * 2 + 1) * Cc + c];
        float g0 = g_gate[n * 2 + 0];
        float g1 = g_gate[n * 2 + 1];
        float comb = g0 * expf(o0) + g1 * expf(o1);
        if (comb == 0.f) comb = EPS_LOGF;
        s[c * 65 + t] = logf(comb);
    }
    __syncthreads();
    for (int idx = tid; idx < Cc * 64; idx += 256) {
        int c = idx >> 6, t = idx & 63;
        d_out[((size_t)(batch * Cc + c)) * HW + hw0 + t] = s[c * 65 + t];
    }
}

// ---------------- launcher ----------------------------------------------------
extern "C" void kernel_launch(void* const* d_in, const int* in_sizes, int n_in,
                              void* d_out, int out_size) {
    const float* x          = (const float*)d_in[0];
    const float* prompt     = (const float*)d_in[1];
    const float* de_cls     = (const float*)d_in[2];
    const float* w_g        = (const float*)d_in[3];
    const float* gate_boost = (const float*)d_in[4];
    const float* degra_w    = (const float*)d_in[5];
    const float* degra_b    = (const float*)d_in[6];
    const float* fc1_w      = (const float*)d_in[7];
    const float* fc1_b      = (const float*)d_in[8];
    const float* fc2_w      = (const float*)d_in[9];
    const float* fc2_b      = (const float*)d_in[10];
    float* out = (float*)d_out;

    cudaFuncSetAttribute(k4_mlp, cudaFuncAttributeMaxDynamicSharedMemorySize,
                         K4_SMEM_FLOATS * sizeof(float));

    k0_bias<<<1, 32>>>(prompt, de_cls, w_g, gate_boost, degra_w, degra_b);
    k1_gate<<<Nn / 64, 256>>>(x, w_g);
    k2_loss<<<1, 256>>>(out, out_size);
    k3_scatter<<<Nn / 256, 256>>>();
    k4_mlp<<<K4_GRID, 256, K4_SMEM_FLOATS * sizeof(float)>>>(fc1_w, fc1_b, fc2_w, fc2_b);
    k5_combine<<<Nn / 64, 256>>>(out);
}

// round 2
// speedup vs baseline: 3.3969x; 3.3969x over previous
#include <cuda_runtime.h>
#include <cuda_bf16.h>
#include <math.h>
#include <stdint.h>

#define Bb 2
#define Cc 128
#define HW 16384
#define Nn 32768
#define Ee 6
#define HFf 512
#define EPS_LOGF 2.220446049250313e-16f

// ---------------- scratch (device globals) ------------------------------------
__device__ uint32_t      g_xf_hi[Nn * 64];      // packed bf16x2 [n][c/2]
__device__ uint32_t      g_xf_lo[Nn * 64];
__device__ float         g_gate[Nn * 2];
__device__ unsigned char g_eidx[Nn * 2];
__device__ int           g_cnt[Ee];
__device__ unsigned long long g_wsum[Ee];
__device__ int           g_off[Ee + 1];
__device__ int           g_cur[Ee];
__device__ unsigned int  g_list[Nn * 2];
__device__ float         g_outbuf[(size_t)Nn * 2 * Cc];
__device__ float         g_bias[Bb * Ee];
__device__ __nv_bfloat16 g_w1t_hi[Ee * HFf * Cc];   // [e][h][c]
__device__ __nv_bfloat16 g_w1t_lo[Ee * HFf * Cc];
__device__ __nv_bfloat16 g_w2t_hi[Ee * Cc * HFf];   // [e][c][h]
__device__ __nv_bfloat16 g_w2t_lo[Ee * Cc * HFf];

// ---------------- helpers -----------------------------------------------------
__device__ __forceinline__ uint32_t smem_u32(const void* p) {
    return (uint32_t)__cvta_generic_to_shared(p);
}
__device__ __forceinline__ void cp16(uint32_t dst, const void* src) {
    asm volatile("cp.async.cg.shared.global [%0], [%1], 16;\n" :: "r"(dst), "l"(src));
}
__device__ __forceinline__ void cp_commit() { asm volatile("cp.async.commit_group;\n"); }
__device__ __forceinline__ void cp_wait0()  { asm volatile("cp.async.wait_group 0;\n"); }

__device__ __forceinline__ void ldm_x4(uint32_t& r0, uint32_t& r1, uint32_t& r2, uint32_t& r3,
                                       uint32_t addr) {
    asm volatile("ldmatrix.sync.aligned.m8n8.x4.shared.b16 {%0,%1,%2,%3}, [%4];\n"
                 : "=r"(r0), "=r"(r1), "=r"(r2), "=r"(r3) : "r"(addr));
}
__device__ __forceinline__ void mma16816(float* c, const uint32_t* a, const uint32_t* b) {
    asm volatile(
        "mma.sync.aligned.m16n8k16.row.col.f32.bf16.bf16.f32 "
        "{%0,%1,%2,%3}, {%4,%5,%6,%7}, {%8,%9}, {%0,%1,%2,%3};\n"
        : "+f"(c[0]), "+f"(c[1]), "+f"(c[2]), "+f"(c[3])
        : "r"(a[0]), "r"(a[1]), "r"(a[2]), "r"(a[3]), "r"(b[0]), "r"(b[1]));
}
__device__ __forceinline__ uint32_t pack_bf2(float v0, float v1) {
    __nv_bfloat16 h0 = __float2bfloat16(v0), h1 = __float2bfloat16(v1);
    return ((uint32_t)__bfloat16_as_ushort(h1) << 16) | __bfloat16_as_ushort(h0);
}

// ---------------- weight prep: fp32 -> transposed bf16 hi/lo ------------------
__global__ __launch_bounds__(256) void kw1(const float* __restrict__ fc1_w) {
    int idx = blockIdx.x * 256 + threadIdx.x;
    if (idx >= Ee * HFf * Cc) return;
    int c = idx & 127, h = (idx >> 7) & 511, e = idx >> 16;
    float v = fc1_w[(size_t)(e * Cc + c) * HFf + h];
    __nv_bfloat16 hi = __float2bfloat16(v);
    g_w1t_hi[idx] = hi;
    g_w1t_lo[idx] = __float2bfloat16(v - __bfloat162float(hi));
}
__global__ __launch_bounds__(256) void kw2(const float* __restrict__ fc2_w) {
    int idx = blockIdx.x * 256 + threadIdx.x;
    if (idx >= Ee * Cc * HFf) return;
    int h = idx & 511, c = (idx >> 9) & 127, e = idx >> 16;
    float v = fc2_w[(size_t)(e * HFf + h) * Cc + c];
    __nv_bfloat16 hi = __float2bfloat16(v);
    g_w2t_hi[idx] = hi;
    g_w2t_lo[idx] = __float2bfloat16(v - __bfloat162float(hi));
}

// ---------------- k0: per-batch gate bias + zero counters ---------------------
__global__ void k0_bias(const float* __restrict__ prompt,
                        const float* __restrict__ de_cls,
                        const float* __restrict__ w_g,
                        const float* __restrict__ gate_boost,
                        const float* __restrict__ degra_w,
                        const float* __restrict__ degra_b) {
    int tid = threadIdx.x;
    if (tid < Ee) { g_cnt[tid] = 0; g_wsum[tid] = 0ULL; }
    if (tid < Bb * Ee) {
        int b = tid / Ee, e = tid % Ee;
        float acc = 0.f;
        for (int c = 0; c < Cc; c++)
            acc += prompt[b * Cc + c] * w_g[(Cc + c) * Ee + e];
        float db = 0.f;
        for (int d = 0; d < Ee; d++)
            db += de_cls[b * Ee + d] * degra_w[d * Ee + e];
        g_bias[b * Ee + e] = acc + gate_boost[0] * (db + degra_b[e]);
    }
}

// ---------------- k1: transpose x -> xf(bf16 hi/lo) + gating + partial sums ---
__global__ __launch_bounds__(256) void k1_gate(const float* __restrict__ x,
                                               const float* __restrict__ w_g) {
    __shared__ float s[Cc * 65];
    __shared__ float wg_s[Cc * Ee];
    __shared__ unsigned long long s_ws[Ee];
    __shared__ int s_ct[Ee];

    int tid = threadIdx.x;
    int n0 = blockIdx.x * 64;
    int batch = n0 >> 14;
    int hw0 = n0 & (HW - 1);

    if (tid < Ee) { s_ws[tid] = 0ULL; s_ct[tid] = 0; }
    for (int i = tid; i < Cc * Ee; i += 256) wg_s[i] = w_g[i];
    for (int idx = tid; idx < Cc * 64; idx += 256) {
        int c = idx >> 6, t = idx & 63;
        s[c * 65 + t] = x[((size_t)(batch * Cc + c)) * HW + hw0 + t];
    }
    __syncthreads();

    for (int idx = tid; idx < 64 * 64; idx += 256) {
        int t = idx >> 6, c2 = idx & 63;
        int c = c2 * 2;
        float v0 = s[c * 65 + t], v1 = s[(c + 1) * 65 + t];
        __nv_bfloat16 h0 = __float2bfloat16(v0), h1 = __float2bfloat16(v1);
        float l0 = v0 - __bfloat162float(h0), l1 = v1 - __bfloat162float(h1);
        g_xf_hi[(size_t)(n0 + t) * 64 + c2] =
            ((uint32_t)__bfloat16_as_ushort(h1) << 16) | __bfloat16_as_ushort(h0);
        g_xf_lo[(size_t)(n0 + t) * 64 + c2] = pack_bf2(l0, l1);
    }

    if (tid < 64) {
        int n = n0 + tid;
        float acc[Ee];
        #pragma unroll
        for (int e = 0; e < Ee; e++) acc[e] = g_bias[batch * Ee + e];
        for (int c = 0; c < Cc; c++) {
            float xv = s[c * 65 + tid];
            #pragma unroll
            for (int e = 0; e < Ee; e++) acc[e] += xv * wg_s[c * Ee + e];
        }
        float v0 = -3.4e38f; int i0 = 0;
        #pragma unroll
        for (int e = 0; e < Ee; e++) if (acc[e] > v0) { v0 = acc[e]; i0 = e; }
        float v1 = -3.4e38f; int i1 = 0;
        #pragma unroll
        for (int e = 0; e < Ee; e++) if (e != i0 && acc[e] > v1) { v1 = acc[e]; i1 = e; }
        float t = expf(v1 - v0);
        float inv = 1.f / (1.f + t);
        float g0c = inv, g1c = t * inv;
        g_eidx[n * 2 + 0] = (unsigned char)i0;
        g_eidx[n * 2 + 1] = (unsigned char)i1;
        g_gate[n * 2 + 0] = g0c;
        g_gate[n * 2 + 1] = g1c;
        atomicAdd(&s_ws[i0], (unsigned long long)llrint((double)g0c * 4294967296.0));
        atomicAdd(&s_ws[i1], (unsigned long long)llrint((double)g1c * 4294967296.0));
        atomicAdd(&s_ct[i0], 1);
        atomicAdd(&s_ct[i1], 1);
    }
    __syncthreads();
    if (tid < Ee) {
        atomicAdd(&g_wsum[tid], s_ws[tid]);
        atomicAdd(&g_cnt[tid], s_ct[tid]);
    }
}

// ---------------- k2: loss + offsets (tiny) -----------------------------------
__global__ void k2_loss(float* __restrict__ d_out, int out_size) {
    if (threadIdx.x == 0) {
        int off = 0;
        double W[Ee], S[Ee];
        for (int e = 0; e < Ee; e++) {
            g_off[e] = off; g_cur[e] = off; off += g_cnt[e];
            W[e] = (double)g_wsum[e] * (1.0 / 4294967296.0);
            S[e] = (double)g_cnt[e];
        }
        g_off[Ee] = off;
        double mW = 0, mS = 0;
        for (int e = 0; e < Ee; e++) { mW += W[e]; mS += S[e]; }
        mW /= Ee; mS /= Ee;
        double vW = 0, vS = 0;
        for (int e = 0; e < Ee; e++) {
            vW += (W[e] - mW) * (W[e] - mW);
            vS += (S[e] - mS) * (S[e] - mS);
        }
        vW /= (Ee - 1); vS /= (Ee - 1);
        double loss = vW / (mW * mW + 1e-10) + vS / (mS * mS + 1e-10);
        if (out_size > Nn * Cc) d_out[Nn * Cc] = (float)loss;
    }
}

// ---------------- k3: scatter with block-local ranking ------------------------
__global__ __launch_bounds__(256) void k3_scatter() {
    __shared__ int c_cnt[Ee], c_base[Ee];
    int tid = threadIdx.x;
    int n = blockIdx.x * 256 + tid;
    if (tid < Ee) c_cnt[tid] = 0;
    __syncthreads();
    int e0 = g_eidx[n * 2], e1 = g_eidx[n * 2 + 1];
    int r0 = atomicAdd(&c_cnt[e0], 1);
    int r1 = atomicAdd(&c_cnt[e1], 1);
    __syncthreads();
    if (tid < Ee) c_base[tid] = atomicAdd(&g_cur[tid], c_cnt[tid]);
    __syncthreads();
    g_list[c_base[e0] + r0] = (unsigned int)(n * 2);
    g_list[c_base[e1] + r1] = (unsigned int)(n * 2 + 1);
}

// ---------------- k4: tensor-core fused MLP -----------------------------------
#define PADK 136
#define SM_AHI 0
#define SM_ALO 8704
#define SM_HHI 17408
#define SM_HLO 26112
#define SM_W0HI 34816
#define SM_W0LO 52224
#define SM_W1HI 69632
#define SM_W1LO 87040
#define K4_SMEM_BYTES (104448 * 2)
#define K4_GRID 1030

__device__ __forceinline__ void load_w_stage(uint32_t smbase, int sm_hi, int sm_lo,
                                             int s, int e, int tid) {
    int hc = s >> 1;
    const __nv_bfloat16 *shi, *slo;
    int rstride;
    if ((s & 1) == 0) {
        shi = g_w1t_hi + ((size_t)e * HFf + hc * 128) * Cc;
        slo = g_w1t_lo + ((size_t)e * HFf + hc * 128) * Cc;
        rstride = Cc;
    } else {
        shi = g_w2t_hi + (size_t)e * Cc * HFf + hc * 128;
        slo = g_w2t_lo + (size_t)e * Cc * HFf + hc * 128;
        rstride = HFf;
    }
    for (int i = tid; i < 2048; i += 256) {
        int r = i >> 4, u = i & 15;
        cp16(smbase + (uint32_t)(sm_hi + r * PADK) * 2 + u * 16, shi + (size_t)r * rstride + u * 8);
        cp16(smbase + (uint32_t)(sm_lo + r * PADK) * 2 + u * 16, slo + (size_t)r * rstride + u * 8);
    }
}

__device__ __forceinline__ void gemm_stage(float (&acc)[2][4][4], uint32_t smbase,
                                           int AHI, int ALO, int WHI, int WLO,
                                           int wm, int wn, int a_r, int a_c,
                                           int b_r, int b_c) {
    #pragma unroll
    for (int kk = 0; kk < 8; kk++) {
        int k = kk * 16;
        uint32_t ah[2][4], al[2][4], bh[4][2], bl[4][2];
        #pragma unroll
        for (int mi = 0; mi < 2; mi++) {
            int row = wm * 32 + mi * 16 + a_r;
            int col = k + a_c;
            ldm_x4(ah[mi][0], ah[mi][1], ah[mi][2], ah[mi][3],
                   smbase + (uint32_t)(AHI + row * PADK + col) * 2);
            ldm_x4(al[mi][0], al[mi][1], al[mi][2], al[mi][3],
                   smbase + (uint32_t)(ALO + row * PADK + col) * 2);
        }
        #pragma unroll
        for (int p = 0; p < 2; p++) {
            int row = wn * 32 + p * 16 + b_r;
            int col = k + b_c;
            uint32_t r0, r1, r2, r3;
            ldm_x4(r0, r1, r2, r3, smbase + (uint32_t)(WHI + row * PADK + col) * 2);
            bh[2 * p][0] = r0; bh[2 * p][1] = r1; bh[2 * p + 1][0] = r2; bh[2 * p + 1][1] = r3;
            ldm_x4(r0, r1, r2, r3, smbase + (uint32_t)(WLO + row * PADK + col) * 2);
            bl[2 * p][0] = r0; bl[2 * p][1] = r1; bl[2 * p + 1][0] = r2; bl[2 * p + 1][1] = r3;
        }
        #pragma unroll
        for (int mi = 0; mi < 2; mi++)
            #pragma unroll
            for (int ni = 0; ni < 4; ni++) {
                mma16816(acc[mi][ni], ah[mi], bh[ni]);
                mma16816(acc[mi][ni], ah[mi], bl[ni]);
                mma16816(acc[mi][ni], al[mi], bh[ni]);
            }
    }
}

__global__ __launch_bounds__(256) void k4_mlp(const float* __restrict__ fc1_b,
                                              const float* __restrict__ fc2_b) {
    extern __shared__ __nv_bfloat16 sm[];
    __shared__ int stoks[64];
    __shared__ int s_meta[3];

    int tid = threadIdx.x;
    if (tid == 0) {
        int rem = blockIdx.x;
        int e = 0, found = 0;
        for (; e < Ee; e++) {
            int t = (g_cnt[e] + 63) >> 6;
            if (rem < t) { found = 1; break; }
            rem -= t;
        }
        if (!found) s_meta[0] = -1;
        else {
            s_meta[0] = e;
            s_meta[1] = g_off[e] + rem * 64;
            int mc = g_cnt[e] - rem * 64;
            s_meta[2] = mc < 64 ? mc : 64;
        }
    }
    __syncthreads();
    int e = s_meta[0];
    if (e < 0) return;
    int base = s_meta[1], mcount = s_meta[2];

    if (tid < 64) {
        int i = tid < mcount ? tid : (mcount - 1);
        stoks[tid] = (int)g_list[base + i];
    }
    __syncthreads();

    uint32_t smbase = smem_u32(sm);

    // prologue: gather A + stage-0 weights
    for (int i = tid; i < 1024; i += 256) {
        int r = i >> 4, u = i & 15;
        int n = stoks[r] >> 1;
        cp16(smbase + (uint32_t)(SM_AHI + r * PADK) * 2 + u * 16, g_xf_hi + (size_t)n * 64 + u * 4);
        cp16(smbase + (uint32_t)(SM_ALO + r * PADK) * 2 + u * 16, g_xf_lo + (size_t)n * 64 + u * 4);
    }
    load_w_stage(smbase, SM_W0HI, SM_W0LO, 0, e, tid);
    cp_commit();
    cp_wait0();
    __syncthreads();

    int lane = tid & 31, warp = tid >> 5;
    int wm = warp & 1, wn = warp >> 1;
    int lg = lane >> 3, lr = lane & 7;
    int a_r = lr + (lg & 1) * 8, a_c = (lg >> 1) * 8;
    int b_r = lr + (lg >> 1) * 8, b_c = (lg & 1) * 8;

    float out_acc[2][4][4];
    #pragma unroll
    for (int mi = 0; mi < 2; mi++)
        #pragma unroll
        for (int ni = 0; ni < 4; ni++)
            #pragma unroll
            for (int q = 0; q < 4; q++) out_acc[mi][ni][q] = 0.f;

    for (int s = 0; s < 8; s++) {
        int buf = s & 1;
        if (s < 7) {
            load_w_stage(smbase, ((s + 1) & 1) ? SM_W1HI : SM_W0HI,
                         ((s + 1) & 1) ? SM_W1LO : SM_W0LO, s + 1, e, tid);
            cp_commit();
        }
        int whi = buf ? SM_W1HI : SM_W0HI;
        int wlo = buf ? SM_W1LO : SM_W0LO;

        if ((s & 1) == 0) {
            // GEMM1 chunk + GELU -> H
            float acc[2][4][4];
            #pragma unroll
            for (int mi = 0; mi < 2; mi++)
                #pragma unroll
                for (int ni = 0; ni < 4; ni++)
                    #pragma unroll
                    for (int q = 0; q < 4; q++) acc[mi][ni][q] = 0.f;
            gemm_stage(acc, smbase, SM_AHI, SM_ALO, whi, wlo, wm, wn, a_r, a_c, b_r, b_c);

            int hb = (s >> 1) * 128;
            #pragma unroll
            for (int ni = 0; ni < 4; ni++) {
                int clocal = wn * 32 + ni * 8 + (lane & 3) * 2;
                float b0f = fc1_b[e * HFf + hb + clocal];
                float b1f = fc1_b[e * HFf + hb + clocal + 1];
                #pragma unroll
                for (int mi = 0; mi < 2; mi++) {
                    int r = wm * 32 + mi * 16 + (lane >> 2);
                    #pragma unroll
                    for (int half = 0; half < 2; half++) {
                        int row = r + half * 8;
                        float v0 = acc[mi][ni][half * 2 + 0] + b0f;
                        float v1 = acc[mi][ni][half * 2 + 1] + b1f;
                        v0 = 0.5f * v0 * (1.f + erff(v0 * 0.7071067811865476f));
                        v1 = 0.5f * v1 * (1.f + erff(v1 * 0.7071067811865476f));
                        __nv_bfloat16 h0 = __float2bfloat16(v0), h1 = __float2bfloat16(v1);
                        float l0 = v0 - __bfloat162float(h0);
                        float l1 = v1 - __bfloat162float(h1);
                        uint32_t ph = ((uint32_t)__bfloat16_as_ushort(h1) << 16) |
                                      __bfloat16_as_ushort(h0);
                        *(uint32_t*)(&sm[SM_HHI + row * PADK + clocal]) = ph;
                        *(uint32_t*)(&sm[SM_HLO + row * PADK + clocal]) = pack_bf2(l0, l1);
                    }
                }
            }
        } else {
            // GEMM2 chunk accumulate
            gemm_stage(out_acc, smbase, SM_HHI, SM_HLO, whi, wlo, wm, wn, a_r, a_c, b_r, b_c);
        }
        cp_wait0();
        __syncthreads();
    }

    // epilogue: + fc2_b, scatter rows to outbuf
    #pragma unroll
    for (int ni = 0; ni < 4; ni++) {
        int col = wn * 32 + ni * 8 + (lane & 3) * 2;
        float b0f = fc2_b[e * Cc + col];
        float b1f = fc2_b[e * Cc + col + 1];
        #pragma unroll
        for (int mi = 0; mi < 2; mi++) {
            int r = wm * 32 + mi * 16 + (lane >> 2);
            #pragma unroll
            for (int half = 0; half < 2; half++) {
                int m = r + half * 8;
                if (m < mcount) {
                    int entry = stoks[m];
                    float2 o;
                    o.x = out_acc[mi][ni][half * 2 + 0] + b0f;
                    o.y = out_acc[mi][ni][half * 2 + 1] + b1f;
                    *(float2*)(g_outbuf + (size_t)entry * Cc + col) = o;
                }
            }
        }
    }
}

// ---------------- k5: combine + transpose out ---------------------------------
__global__ __launch_bounds__(256) void k5_combine(float* __restrict__ d_out) {
    __shared__ float s[Cc * 65];
    int tid = threadIdx.x;
    int n0 = blockIdx.x * 64;
    int batch = n0 >> 14;
    int hw0 = n0 & (HW - 1);

    for (int idx = tid; idx < 64 * Cc; idx += 256) {
        int t = idx >> 7, c = idx & 127;
        int n = n0 + t;
        float o0 = g_outbuf[(size_t)(n * 2 + 0) * Cc + c];
        float o1 = g_outbuf[(size_t)(n * 2 + 1) * Cc + c];
        float g0 = g_gate[n * 2 + 0];
        float g1 = g_gate[n * 2 + 1];
        float comb = g0 * expf(o0) + g1 * expf(o1);
        if (comb == 0.f) comb = EPS_LOGF;
        s[c * 65 + t] = logf(comb);
    }
    __syncthreads();
    for (int idx = tid; idx < Cc * 64; idx += 256) {
        int c = idx >> 6, t = idx & 63;
        d_out[((size_t)(batch * Cc + c)) * HW + hw0 + t] = s[c * 65 + t];
    }
}

// ---------------- launcher ----------------------------------------------------
extern "C" void kernel_launch(void* const* d_in, const int* in_sizes, int n_in,
                              void* d_out, int out_size) {
    const float* x          = (const float*)d_in[0];
    const float* prompt     = (const float*)d_in[1];
    const float* de_cls     = (const float*)d_in[2];
    const float* w_g        = (const float*)d_in[3];
    const float* gate_boost = (const float*)d_in[4];
    const float* degra_w    = (const float*)d_in[5];
    const float* degra_b    = (const float*)d_in[6];
    const float* fc1_w      = (const float*)d_in[7];
    const float* fc1_b      = (const float*)d_in[8];
    const float* fc2_w      = (const float*)d_in[9];
    const float* fc2_b      = (const float*)d_in[10];
    float* out = (float*)d_out;

    cudaFuncSetAttribute(k4_mlp, cudaFuncAttributeMaxDynamicSharedMemorySize,
                         K4_SMEM_BYTES);

    kw1<<<(Ee * HFf * Cc + 255) / 256, 256>>>(fc1_w);
    kw2<<<(Ee * Cc * HFf + 255) / 256, 256>>>(fc2_w);
    k0_bias<<<1, 32>>>(prompt, de_cls, w_g, gate_boost, degra_w, degra_b);
    k1_gate<<<Nn / 64, 256>>>(x, w_g);
    k2_loss<<<1, 32>>>(out, out_size);
    k3_scatter<<<Nn / 256, 256>>>();
    k4_mlp<<<K4_GRID, 256, K4_SMEM_BYTES>>>(fc1_b, fc2_b);
    k5_combine<<<Nn / 64, 256>>>(out);
}

// round 4
// speedup vs baseline: 4.7627x; 1.4021x over previous
#include <cuda_runtime.h>
#include <cuda_fp16.h>
#include <math.h>
#include <stdint.h>

#define Bb 2
#define Cc 128
#define HW 16384
#define Nn 32768
#define Ee 6
#define HFf 512
#define EPS_LOGF 2.220446049250313e-16f

// ---------------- scratch (device globals) ------------------------------------
__device__ __align__(256) uint32_t      g_xf_hi[Nn * 64];   // packed fp16x2 [n][c/2]
__device__ __align__(256) uint32_t      g_xf_lo[Nn * 64];
__device__ float         g_gate[Nn * 2];
__device__ unsigned char g_eidx[Nn * 2];
__device__ int           g_cnt[Ee];
__device__ unsigned long long g_wsum[Ee];
__device__ int           g_off[Ee + 1];
__device__ int           g_cur[Ee];
__device__ unsigned int  g_list[Nn * 2];
__device__ float         g_outbuf[(size_t)Nn * 2 * Cc];
__device__ float         g_bias[Bb * Ee];
__device__ __align__(256) __half g_w1t[Ee * HFf * Cc];   // [e][h][c] fp16
__device__ __align__(256) __half g_w2t[Ee * Cc * HFf];   // [e][c][h] fp16

// ---------------- helpers -----------------------------------------------------
__device__ __forceinline__ uint32_t smem_u32(const void* p) {
    return (uint32_t)__cvta_generic_to_shared(p);
}
__device__ __forceinline__ void cp16(uint32_t dst, const void* src) {
    asm volatile("cp.async.cg.shared.global [%0], [%1], 16;\n" :: "r"(dst), "l"(src));
}
__device__ __forceinline__ void cp_commit() { asm volatile("cp.async.commit_group;\n"); }
__device__ __forceinline__ void cp_wait0()  { asm volatile("cp.async.wait_group 0;\n"); }

__device__ __forceinline__ void ldm_x4(uint32_t& r0, uint32_t& r1, uint32_t& r2, uint32_t& r3,
                                       uint32_t addr) {
    asm volatile("ldmatrix.sync.aligned.m8n8.x4.shared.b16 {%0,%1,%2,%3}, [%4];\n"
                 : "=r"(r0), "=r"(r1), "=r"(r2), "=r"(r3) : "r"(addr));
}
__device__ __forceinline__ void mma16816(float* c, const uint32_t* a, const uint32_t* b) {
    asm volatile(
        "mma.sync.aligned.m16n8k16.row.col.f32.f16.f16.f32 "
        "{%0,%1,%2,%3}, {%4,%5,%6,%7}, {%8,%9}, {%0,%1,%2,%3};\n"
        : "+f"(c[0]), "+f"(c[1]), "+f"(c[2]), "+f"(c[3])
        : "r"(a[0]), "r"(a[1]), "r"(a[2]), "r"(a[3]), "r"(b[0]), "r"(b[1]));
}
__device__ __forceinline__ uint32_t pack_h2(float v0, float v1) {
    __half h0 = __float2half_rn(v0), h1 = __float2half_rn(v1);
    return ((uint32_t)__half_as_ushort(h1) << 16) | __half_as_ushort(h0);
}

// ---------------- weight prep: tiled transpose fp32 -> fp16 -------------------
__global__ __launch_bounds__(256) void kw1(const float* __restrict__ fc1_w) {
    __shared__ float t[32][33];
    int bz = blockIdx.x;                       // e*64 + (h/32)*4 + (c/32)
    int e = bz >> 6, r = bz & 63;
    int hb = (r >> 2) * 32, cb = (r & 3) * 32;
    int tid = threadIdx.x;
    for (int i = tid; i < 1024; i += 256) {
        int c = i >> 5, h = i & 31;
        t[c][h] = fc1_w[((size_t)(e * Cc + cb + c)) * HFf + hb + h];
    }
    __syncthreads();
    for (int i = tid; i < 1024; i += 256) {
        int h = i >> 5, c = i & 31;
        g_w1t[((size_t)(e * HFf + hb + h)) * Cc + cb + c] = __float2half_rn(t[c][h]);
    }
}
__global__ __launch_bounds__(256) void kw2(const float* __restrict__ fc2_w) {
    __shared__ float t[32][33];
    int bz = blockIdx.x;
    int e = bz >> 6, r = bz & 63;
    int hb = (r >> 2) * 32, cb = (r & 3) * 32;
    int tid = threadIdx.x;
    for (int i = tid; i < 1024; i += 256) {
        int h = i >> 5, c = i & 31;
        t[h][c] = fc2_w[((size_t)(e * HFf + hb + h)) * Cc + cb + c];
    }
    __syncthreads();
    for (int i = tid; i < 1024; i += 256) {
        int c = i >> 5, h = i & 31;
        g_w2t[((size_t)(e * Cc + cb + c)) * HFf + hb + h] = __float2half_rn(t[h][c]);
    }
}

// ---------------- k0: per-batch gate bias + zero counters ---------------------
__global__ void k0_bias(const float* __restrict__ prompt,
                        const float* __restrict__ de_cls,
                        const float* __restrict__ w_g,
                        const float* __restrict__ gate_boost,
                        const float* __restrict__ degra_w,
                        const float* __restrict__ degra_b) {
    int tid = threadIdx.x;
    if (tid < Ee) { g_cnt[tid] = 0; g_wsum[tid] = 0ULL; }
    if (tid < Bb * Ee) {
        int b = tid / Ee, e = tid % Ee;
        float acc = 0.f;
        for (int c = 0; c < Cc; c++)
            acc += prompt[b * Cc + c] * w_g[(Cc + c) * Ee + e];
        float db = 0.f;
        for (int d = 0; d < Ee; d++)
            db += de_cls[b * Ee + d] * degra_w[d * Ee + e];
        g_bias[b * Ee + e] = acc + gate_boost[0] * (db + degra_b[e]);
    }
}

// ---------------- k1: transpose + xf fp16 hi/lo + gating ----------------------
__global__ __launch_bounds__(256) void k1_gate(const float* __restrict__ x,
                                               const float* __restrict__ w_g) {
    __shared__ float s[Cc * 65];
    __shared__ float wg_s[Cc * Ee];
    __shared__ unsigned long long s_ws[Ee];
    __shared__ int s_ct[Ee];

    int tid = threadIdx.x;
    int n0 = blockIdx.x * 64;
    int batch = n0 >> 14;
    int hw0 = n0 & (HW - 1);

    if (tid < Ee) { s_ws[tid] = 0ULL; s_ct[tid] = 0; }
    for (int i = tid; i < Cc * Ee; i += 256) wg_s[i] = w_g[i];
    for (int idx = tid; idx < Cc * 64; idx += 256) {
        int c = idx >> 6, t = idx & 63;
        s[c * 65 + t] = x[((size_t)(batch * Cc + c)) * HW + hw0 + t];
    }
    __syncthreads();

    for (int idx = tid; idx < 64 * 64; idx += 256) {
        int t = idx >> 6, c2 = idx & 63;
        int c = c2 * 2;
        float v0 = s[c * 65 + t], v1 = s[(c + 1) * 65 + t];
        __half h0 = __float2half_rn(v0), h1 = __float2half_rn(v1);
        g_xf_hi[(size_t)(n0 + t) * 64 + c2] =
            ((uint32_t)__half_as_ushort(h1) << 16) | __half_as_ushort(h0);
        g_xf_lo[(size_t)(n0 + t) * 64 + c2] =
            pack_h2(v0 - __half2float(h0), v1 - __half2float(h1));
    }

    {
        int t = tid >> 2, q = tid & 3;
        float acc[Ee];
        #pragma unroll
        for (int e = 0; e < Ee; e++) acc[e] = 0.f;
        #pragma unroll 4
        for (int cc = 0; cc < 32; cc++) {
            int c = q * 32 + cc;
            float xv = s[c * 65 + t];
            #pragma unroll
            for (int e = 0; e < Ee; e++) acc[e] += xv * wg_s[c * Ee + e];
        }
        #pragma unroll
        for (int e = 0; e < Ee; e++) {
            acc[e] += __shfl_xor_sync(0xFFFFFFFFu, acc[e], 1);
            acc[e] += __shfl_xor_sync(0xFFFFFFFFu, acc[e], 2);
        }
        if (q == 0) {
            int n = n0 + t;
            #pragma unroll
            for (int e = 0; e < Ee; e++) acc[e] += g_bias[batch * Ee + e];
            float v0 = -3.4e38f; int i0 = 0;
            #pragma unroll
            for (int e = 0; e < Ee; e++) if (acc[e] > v0) { v0 = acc[e]; i0 = e; }
            float v1 = -3.4e38f; int i1 = 0;
            #pragma unroll
            for (int e = 0; e < Ee; e++) if (e != i0 && acc[e] > v1) { v1 = acc[e]; i1 = e; }
            float tt = expf(v1 - v0);
            float inv = 1.f / (1.f + tt);
            float g0c = inv, g1c = tt * inv;
            g_eidx[n * 2 + 0] = (unsigned char)i0;
            g_eidx[n * 2 + 1] = (unsigned char)i1;
            g_gate[n * 2 + 0] = g0c;
            g_gate[n * 2 + 1] = g1c;
            atomicAdd(&s_ws[i0], (unsigned long long)llrint((double)g0c * 4294967296.0));
            atomicAdd(&s_ws[i1], (unsigned long long)llrint((double)g1c * 4294967296.0));
            atomicAdd(&s_ct[i0], 1);
            atomicAdd(&s_ct[i1], 1);
        }
    }
    __syncthreads();
    if (tid < Ee) {
        atomicAdd(&g_wsum[tid], s_ws[tid]);
        atomicAdd(&g_cnt[tid], s_ct[tid]);
    }
}

// ---------------- k2: loss + offsets ------------------------------------------
__global__ void k2_loss(float* __restrict__ d_out, int out_size) {
    if (threadIdx.x == 0) {
        int off = 0;
        double W[Ee], S[Ee];
        for (int e = 0; e < Ee; e++) {
            g_off[e] = off; g_cur[e] = off; off += g_cnt[e];
            W[e] = (double)g_wsum[e] * (1.0 / 4294967296.0);
            S[e] = (double)g_cnt[e];
        }
        g_off[Ee] = off;
        double mW = 0, mS = 0;
        for (int e = 0; e < Ee; e++) { mW += W[e]; mS += S[e]; }
        mW /= Ee; mS /= Ee;
        double vW = 0, vS = 0;
        for (int e = 0; e < Ee; e++) {
            vW += (W[e] - mW) * (W[e] - mW);
            vS += (S[e] - mS) * (S[e] - mS);
        }
        vW /= (Ee - 1); vS /= (Ee - 1);
        double loss = vW / (mW * mW + 1e-10) + vS / (mS * mS + 1e-10);
        if (out_size > Nn * Cc) d_out[Nn * Cc] = (float)loss;
    }
}

// ---------------- k3: scatter --------------------------------------------------
__global__ __launch_bounds__(256) void k3_scatter() {
    __shared__ int c_cnt[Ee], c_base[Ee];
    int tid = threadIdx.x;
    int n = blockIdx.x * 256 + tid;
    if (tid < Ee) c_cnt[tid] = 0;
    __syncthreads();
    int e0 = g_eidx[n * 2], e1 = g_eidx[n * 2 + 1];
    int r0 = atomicAdd(&c_cnt[e0], 1);
    int r1 = atomicAdd(&c_cnt[e1], 1);
    __syncthreads();
    if (tid < Ee) c_base[tid] = atomicAdd(&g_cur[tid], c_cnt[tid]);
    __syncthreads();
    g_list[c_base[e0] + r0] = (unsigned int)(n * 2);
    g_list[c_base[e1] + r1] = (unsigned int)(n * 2 + 1);
}

// ---------------- k4: fp16 2-term tensor-core fused MLP -----------------------
// 64 tokens per block, single W buffer, 102 KB smem -> 2 blocks/SM.
#define PADK 136
#define SM_AHI 0
#define SM_ALO 8704
#define SM_HHI 17408
#define SM_HLO 26112
#define SM_W   34816
#define K4_SMEM_BYTES ((34816 + 17408) * 2)
#define K4_GRID 1030

__device__ __forceinline__ void load_wchunk(uint32_t smbase, const __half* src,
                                            int rstride, int t0, int stride) {
    for (int i = t0; i < 2048; i += stride) {
        int r = i >> 4, u = i & 15;
        cp16(smbase + (uint32_t)(SM_W + r * PADK) * 2 + u * 16,
             src + (size_t)r * rstride + u * 8);
    }
}

__device__ __forceinline__ void gemm_stage(float (&acc)[2][4][4], uint32_t smbase,
                                           int AHI, int ALO,
                                           int wm, int wn, int a_r, int a_c,
                                           int b_r, int b_c) {
    #pragma unroll
    for (int kk = 0; kk < 8; kk++) {
        int k = kk * 16;
        uint32_t ah[2][4], al[2][4], bw[4][2];
        #pragma unroll
        for (int mi = 0; mi < 2; mi++) {
            int row = wm * 32 + mi * 16 + a_r;
            int col = k + a_c;
            ldm_x4(ah[mi][0], ah[mi][1], ah[mi][2], ah[mi][3],
                   smbase + (uint32_t)(AHI + row * PADK + col) * 2);
            ldm_x4(al[mi][0], al[mi][1], al[mi][2], al[mi][3],
                   smbase + (uint32_t)(ALO + row * PADK + col) * 2);
        }
        #pragma unroll
        for (int p = 0; p < 2; p++) {
            int row = wn * 32 + p * 16 + b_r;
            int col = k + b_c;
            uint32_t r0, r1, r2, r3;
            ldm_x4(r0, r1, r2, r3, smbase + (uint32_t)(SM_W + row * PADK + col) * 2);
            bw[2 * p][0] = r0; bw[2 * p][1] = r1; bw[2 * p + 1][0] = r2; bw[2 * p + 1][1] = r3;
        }
        #pragma unroll
        for (int mi = 0; mi < 2; mi++)
            #pragma unroll
            for (int ni = 0; ni < 4; ni++) {
                mma16816(acc[mi][ni], ah[mi], bw[ni]);
                mma16816(acc[mi][ni], al[mi], bw[ni]);
            }
    }
}

__global__ __launch_bounds__(256, 2) void k4_mlp(const float* __restrict__ fc1_b,
                                                 const float* __restrict__ fc2_b) {
    extern __shared__ __half sm[];
    __shared__ int stoks[64];
    __shared__ int s_meta[3];
    __shared__ float s_b1[128];

    int tid = threadIdx.x;
    if (tid == 0) {
        int rem = blockIdx.x;
        int e = 0, found = 0;
        for (; e < Ee; e++) {
            int t = (g_cnt[e] + 63) >> 6;
            if (rem < t) { found = 1; break; }
            rem -= t;
        }
        if (!found) s_meta[0] = -1;
        else {
            s_meta[0] = e;
            s_meta[1] = g_off[e] + rem * 64;
            int mc = g_cnt[e] - rem * 64;
            s_meta[2] = mc < 64 ? mc : 64;
        }
    }
    __syncthreads();
    int e = s_meta[0];
    if (e < 0) return;
    int base = s_meta[1], mcount = s_meta[2];

    if (tid < 64) {
        int i = tid < mcount ? tid : (mcount - 1);
        stoks[tid] = (int)g_list[base + i];
    }
    __syncthreads();

    uint32_t smbase = smem_u32(sm);

    // prologue: gather A hi/lo + W1 chunk 0
    for (int i = tid; i < 1024; i += 256) {
        int r = i >> 4, u = i & 15;
        int n = stoks[r] >> 1;
        cp16(smbase + (uint32_t)(SM_AHI + r * PADK) * 2 + u * 16, g_xf_hi + (size_t)n * 64 + u * 4);
        cp16(smbase + (uint32_t)(SM_ALO + r * PADK) * 2 + u * 16, g_xf_lo + (size_t)n * 64 + u * 4);
    }
    load_wchunk(smbase, g_w1t + (size_t)e * HFf * Cc, Cc, tid, 256);
    cp_commit();
    cp_wait0();
    __syncthreads();

    int lane = tid & 31, warp = tid >> 5;
    int wm = warp & 1, wn = warp >> 1;
    int lg = lane >> 3, lr = lane & 7;
    int a_r = lr + (lg & 1) * 8, a_c = (lg >> 1) * 8;
    int b_r = lr + (lg >> 1) * 8, b_c = (lg & 1) * 8;

    float out_acc[2][4][4];
    #pragma unroll
    for (int mi = 0; mi < 2; mi++)
        #pragma unroll
        for (int ni = 0; ni < 4; ni++)
            #pragma unroll
            for (int q = 0; q < 4; q++) out_acc[mi][ni][q] = 0.f;

    for (int hc = 0; hc < 4; hc++) {
        int hb = hc * 128;
        // ---- GEMM1 chunk (W buffer holds W1[hb:hb+128][c]) ----
        float acc[2][4][4];
        #pragma unroll
        for (int mi = 0; mi < 2; mi++)
            #pragma unroll
            for (int ni = 0; ni < 4; ni++)
                #pragma unroll
                for (int q = 0; q < 4; q++) acc[mi][ni][q] = 0.f;
        gemm_stage(acc, smbase, SM_AHI, SM_ALO, wm, wn, a_r, a_c, b_r, b_c);
        if (tid < 128) s_b1[tid] = fc1_b[e * HFf + hb + tid];
        __syncthreads();                    // W buffer free

        // start W2 chunk load into W buffer
        load_wchunk(smbase, g_w2t + (size_t)e * Cc * HFf + hb, HFf, tid, 256);
        cp_commit();

        // epilogue: bias + GELU -> H hi/lo smem (doesn't touch W)
        #pragma unroll
        for (int ni = 0; ni < 4; ni++) {
            int clocal = wn * 32 + ni * 8 + (lane & 3) * 2;
            float b0f = s_b1[clocal];
            float b1f = s_b1[clocal + 1];
            #pragma unroll
            for (int mi = 0; mi < 2; mi++) {
                int r = wm * 32 + mi * 16 + (lane >> 2);
                #pragma unroll
                for (int half = 0; half < 2; half++) {
                    int row = r + half * 8;
                    float v0 = acc[mi][ni][half * 2 + 0] + b0f;
                    float v1 = acc[mi][ni][half * 2 + 1] + b1f;
                    v0 = 0.5f * v0 * (1.f + erff(v0 * 0.7071067811865476f));
                    v1 = 0.5f * v1 * (1.f + erff(v1 * 0.7071067811865476f));
                    __half h0 = __float2half_rn(v0), h1 = __float2half_rn(v1);
                    *(uint32_t*)(&sm[SM_HHI + row * PADK + clocal]) =
                        ((uint32_t)__half_as_ushort(h1) << 16) | __half_as_ushort(h0);
                    *(uint32_t*)(&sm[SM_HLO + row * PADK + clocal]) =
                        pack_h2(v0 - __half2float(h0), v1 - __half2float(h1));
                }
            }
        }
        cp_wait0();
        __syncthreads();                    // H visible, W2 ready

        // ---- GEMM2 chunk accumulate ----
        gemm_stage(out_acc, smbase, SM_HHI, SM_HLO, wm, wn, a_r, a_c, b_r, b_c);
        __syncthreads();                    // W buffer free

        if (hc < 3) {
            load_wchunk(smbase, g_w1t + ((size_t)e * HFf + hb + 128) * Cc, Cc, tid, 256);
            cp_commit();
            cp_wait0();
            __syncthreads();
        }
    }

    // epilogue: + fc2_b, scatter rows to outbuf
    #pragma unroll
    for (int ni = 0; ni < 4; ni++) {
        int col = wn * 32 + ni * 8 + (lane & 3) * 2;
        float b0f = fc2_b[e * Cc + col];
        float b1f = fc2_b[e * Cc + col + 1];
        #pragma unroll
        for (int mi = 0; mi < 2; mi++) {
            int r = wm * 32 + mi * 16 + (lane >> 2);
            #pragma unroll
            for (int half = 0; half < 2; half++) {
                int m = r + half * 8;
                if (m < mcount) {
                    int entry = stoks[m];
                    float2 o;
                    o.x = out_acc[mi][ni][half * 2 + 0] + b0f;
                    o.y = out_acc[mi][ni][half * 2 + 1] + b1f;
                    *(float2*)(g_outbuf + (size_t)entry * Cc + col) = o;
                }
            }
        }
    }
}

// ---------------- k5: combine + transpose out ----------------------------------
__global__ __launch_bounds__(256) void k5_combine(float* __restrict__ d_out) {
    __shared__ float s[Cc * 65];
    int tid = threadIdx.x;
    int n0 = blockIdx.x * 64;
    int batch = n0 >> 14;
    int hw0 = n0 & (HW - 1);

    for (int idx = tid; idx < 64 * Cc; idx += 256) {
        int t = idx >> 7, c = idx & 127;
        int n = n0 + t;
        float o0 = g_outbuf[(size_t)(n * 2 + 0) * Cc + c];
        float o1 = g_outbuf[(size_t)(n * 2 + 1) * Cc + c];
        float g0 = g_gate[n * 2 + 0];
        float g1 = g_gate[n * 2 + 1];
        float comb = g0 * expf(o0) + g1 * expf(o1);
        if (comb == 0.f) comb = EPS_LOGF;
        s[c * 65 + t] = logf(comb);
    }
    __syncthreads();
    for (int idx = tid; idx < Cc * 64; idx += 256) {
        int c = idx >> 6, t = idx & 63;
        d_out[((size_t)(batch * Cc + c)) * HW + hw0 + t] = s[c * 65 + t];
    }
}

// ---------------- launcher ------------------------------------------------------
extern "C" void kernel_launch(void* const* d_in, const int* in_sizes, int n_in,
                              void* d_out, int out_size) {
    const float* x          = (const float*)d_in[0];
    const float* prompt     = (const float*)d_in[1];
    const float* de_cls     = (const float*)d_in[2];
    const float* w_g        = (const float*)d_in[3];
    const float* gate_boost = (const float*)d_in[4];
    const float* degra_w    = (const float*)d_in[5];
    const float* degra_b    = (const float*)d_in[6];
    const float* fc1_w      = (const float*)d_in[7];
    const float* fc1_b      = (const float*)d_in[8];
    const float* fc2_w      = (const float*)d_in[9];
    const float* fc2_b      = (const float*)d_in[10];
    float* out = (float*)d_out;

    cudaFuncSetAttribute(k4_mlp, cudaFuncAttributeMaxDynamicSharedMemorySize,
                         K4_SMEM_BYTES);

    kw1<<<Ee * 64, 256>>>(fc1_w);
    kw2<<<Ee * 64, 256>>>(fc2_w);
    k0_bias<<<1, 32>>>(prompt, de_cls, w_g, gate_boost, degra_w, degra_b);
    k1_gate<<<Nn / 64, 256>>>(x, w_g);
    k2_loss<<<1, 32>>>(out, out_size);
    k3_scatter<<<Nn / 256, 256>>>();
    k4_mlp<<<K4_GRID, 256, K4_SMEM_BYTES>>>(fc1_b, fc2_b);
    k5_combine<<<Nn / 64, 256>>>(out);
}

// round 5
// speedup vs baseline: 4.7921x; 1.0062x over previous
#include <cuda_runtime.h>
#include <cuda_fp16.h>
#include <math.h>
#include <stdint.h>

#define Bb 2
#define Cc 128
#define HW 16384
#define Nn 32768
#define Ee 6
#define HFf 512
#define EPS_LOGF 2.220446049250313e-16f

// ---------------- scratch (device globals) ------------------------------------
__device__ __align__(256) uint32_t      g_xf_hi[Nn * 64];   // packed fp16x2 [n][c/2]
__device__ __align__(256) uint32_t      g_xf_lo[Nn * 64];
__device__ float         g_gate[Nn * 2];
__device__ unsigned char g_eidx[Nn * 2];
__device__ int           g_cnt[Ee];
__device__ unsigned long long g_wsum[Ee];
__device__ int           g_off[Ee + 1];
__device__ int           g_cur[Ee];
__device__ unsigned int  g_list[Nn * 2];
__device__ float         g_outbuf[(size_t)Nn * 2 * Cc];
__device__ float         g_bias[Bb * Ee];
__device__ __align__(256) __half g_w1t[Ee * HFf * Cc];   // [e][h][c] fp16
__device__ __align__(256) __half g_w2t[Ee * Cc * HFf];   // [e][c][h] fp16

// ---------------- helpers -----------------------------------------------------
__device__ __forceinline__ uint32_t smem_u32(const void* p) {
    return (uint32_t)__cvta_generic_to_shared(p);
}
__device__ __forceinline__ void cp16(uint32_t dst, const void* src) {
    asm volatile("cp.async.cg.shared.global [%0], [%1], 16;\n" :: "r"(dst), "l"(src));
}
__device__ __forceinline__ void cp_commit() { asm volatile("cp.async.commit_group;\n"); }
__device__ __forceinline__ void cp_wait0()  { asm volatile("cp.async.wait_group 0;\n"); }

__device__ __forceinline__ void ldm_x4(uint32_t& r0, uint32_t& r1, uint32_t& r2, uint32_t& r3,
                                       uint32_t addr) {
    asm volatile("ldmatrix.sync.aligned.m8n8.x4.shared.b16 {%0,%1,%2,%3}, [%4];\n"
                 : "=r"(r0), "=r"(r1), "=r"(r2), "=r"(r3) : "r"(addr));
}
__device__ __forceinline__ void mma16816(float* c, const uint32_t* a, const uint32_t* b) {
    asm volatile(
        "mma.sync.aligned.m16n8k16.row.col.f32.f16.f16.f32 "
        "{%0,%1,%2,%3}, {%4,%5,%6,%7}, {%8,%9}, {%0,%1,%2,%3};\n"
        : "+f"(c[0]), "+f"(c[1]), "+f"(c[2]), "+f"(c[3])
        : "r"(a[0]), "r"(a[1]), "r"(a[2]), "r"(a[3]), "r"(b[0]), "r"(b[1]));
}
__device__ __forceinline__ uint32_t pack_h2(float v0, float v1) {
    __half h0 = __float2half_rn(v0), h1 = __float2half_rn(v1);
    return ((uint32_t)__half_as_ushort(h1) << 16) | __half_as_ushort(h0);
}

// ---------------- weight prep: tiled transpose fp32 -> fp16 -------------------
__global__ __launch_bounds__(256) void kw1(const float* __restrict__ fc1_w) {
    __shared__ float t[32][33];
    int bz = blockIdx.x;                       // e*64 + (h/32)*4 + (c/32)
    int e = bz >> 6, r = bz & 63;
    int hb = (r >> 2) * 32, cb = (r & 3) * 32;
    int tid = threadIdx.x;
    for (int i = tid; i < 1024; i += 256) {
        int c = i >> 5, h = i & 31;
        t[c][h] = fc1_w[((size_t)(e * Cc + cb + c)) * HFf + hb + h];
    }
    __syncthreads();
    for (int i = tid; i < 1024; i += 256) {
        int h = i >> 5, c = i & 31;
        g_w1t[((size_t)(e * HFf + hb + h)) * Cc + cb + c] = __float2half_rn(t[c][h]);
    }
}
__global__ __launch_bounds__(256) void kw2(const float* __restrict__ fc2_w) {
    __shared__ float t[32][33];
    int bz = blockIdx.x;
    int e = bz >> 6, r = bz & 63;
    int hb = (r >> 2) * 32, cb = (r & 3) * 32;
    int tid = threadIdx.x;
    for (int i = tid; i < 1024; i += 256) {
        int h = i >> 5, c = i & 31;
        t[h][c] = fc2_w[((size_t)(e * HFf + hb + h)) * Cc + cb + c];
    }
    __syncthreads();
    for (int i = tid; i < 1024; i += 256) {
        int c = i >> 5, h = i & 31;
        g_w2t[((size_t)(e * Cc + cb + c)) * HFf + hb + h] = __float2half_rn(t[h][c]);
    }
}

// ---------------- k0: per-batch gate bias + zero counters ---------------------
__global__ void k0_bias(const float* __restrict__ prompt,
                        const float* __restrict__ de_cls,
                        const float* __restrict__ w_g,
                        const float* __restrict__ gate_boost,
                        const float* __restrict__ degra_w,
                        const float* __restrict__ degra_b) {
    int tid = threadIdx.x;
    if (tid < Ee) { g_cnt[tid] = 0; g_wsum[tid] = 0ULL; }
    if (tid < Bb * Ee) {
        int b = tid / Ee, e = tid % Ee;
        float acc = 0.f;
        for (int c = 0; c < Cc; c++)
            acc += prompt[b * Cc + c] * w_g[(Cc + c) * Ee + e];
        float db = 0.f;
        for (int d = 0; d < Ee; d++)
            db += de_cls[b * Ee + d] * degra_w[d * Ee + e];
        g_bias[b * Ee + e] = acc + gate_boost[0] * (db + degra_b[e]);
    }
}

// ---------------- k1: transpose + xf fp16 hi/lo + gating ----------------------
__global__ __launch_bounds__(256) void k1_gate(const float* __restrict__ x,
                                               const float* __restrict__ w_g) {
    __shared__ float s[Cc * 65];
    __shared__ float wg_s[Cc * Ee];
    __shared__ unsigned long long s_ws[Ee];
    __shared__ int s_ct[Ee];

    int tid = threadIdx.x;
    int n0 = blockIdx.x * 64;
    int batch = n0 >> 14;
    int hw0 = n0 & (HW - 1);

    if (tid < Ee) { s_ws[tid] = 0ULL; s_ct[tid] = 0; }
    for (int i = tid; i < Cc * Ee; i += 256) wg_s[i] = w_g[i];
    for (int idx = tid; idx < Cc * 64; idx += 256) {
        int c = idx >> 6, t = idx & 63;
        s[c * 65 + t] = x[((size_t)(batch * Cc + c)) * HW + hw0 + t];
    }
    __syncthreads();

    for (int idx = tid; idx < 64 * 64; idx += 256) {
        int t = idx >> 6, c2 = idx & 63;
        int c = c2 * 2;
        float v0 = s[c * 65 + t], v1 = s[(c + 1) * 65 + t];
        __half h0 = __float2half_rn(v0), h1 = __float2half_rn(v1);
        g_xf_hi[(size_t)(n0 + t) * 64 + c2] =
            ((uint32_t)__half_as_ushort(h1) << 16) | __half_as_ushort(h0);
        g_xf_lo[(size_t)(n0 + t) * 64 + c2] =
            pack_h2(v0 - __half2float(h0), v1 - __half2float(h1));
    }

    {
        int t = tid >> 2, q = tid & 3;
        float acc[Ee];
        #pragma unroll
        for (int e = 0; e < Ee; e++) acc[e] = 0.f;
        #pragma unroll 4
        for (int cc = 0; cc < 32; cc++) {
            int c = q * 32 + cc;
            float xv = s[c * 65 + t];
            #pragma unroll
            for (int e = 0; e < Ee; e++) acc[e] += xv * wg_s[c * Ee + e];
        }
        #pragma unroll
        for (int e = 0; e < Ee; e++) {
            acc[e] += __shfl_xor_sync(0xFFFFFFFFu, acc[e], 1);
            acc[e] += __shfl_xor_sync(0xFFFFFFFFu, acc[e], 2);
        }
        if (q == 0) {
            int n = n0 + t;
            #pragma unroll
            for (int e = 0; e < Ee; e++) acc[e] += g_bias[batch * Ee + e];
            float v0 = -3.4e38f; int i0 = 0;
            #pragma unroll
            for (int e = 0; e < Ee; e++) if (acc[e] > v0) { v0 = acc[e]; i0 = e; }
            float v1 = -3.4e38f; int i1 = 0;
            #pragma unroll
            for (int e = 0; e < Ee; e++) if (e != i0 && acc[e] > v1) { v1 = acc[e]; i1 = e; }
            float tt = expf(v1 - v0);
            float inv = 1.f / (1.f + tt);
            float g0c = inv, g1c = tt * inv;
            g_eidx[n * 2 + 0] = (unsigned char)i0;
            g_eidx[n * 2 + 1] = (unsigned char)i1;
            g_gate[n * 2 + 0] = g0c;
            g_gate[n * 2 + 1] = g1c;
            atomicAdd(&s_ws[i0], (unsigned long long)llrint((double)g0c * 4294967296.0));
            atomicAdd(&s_ws[i1], (unsigned long long)llrint((double)g1c * 4294967296.0));
            atomicAdd(&s_ct[i0], 1);
            atomicAdd(&s_ct[i1], 1);
        }
    }
    __syncthreads();
    if (tid < Ee) {
        atomicAdd(&g_wsum[tid], s_ws[tid]);
        atomicAdd(&g_cnt[tid], s_ct[tid]);
    }
}

// ---------------- k2: loss + offsets ------------------------------------------
__global__ void k2_loss(float* __restrict__ d_out, int out_size) {
    if (threadIdx.x == 0) {
        int off = 0;
        double W[Ee], S[Ee];
        for (int e = 0; e < Ee; e++) {
            g_off[e] = off; g_cur[e] = off; off += g_cnt[e];
            W[e] = (double)g_wsum[e] * (1.0 / 4294967296.0);
            S[e] = (double)g_cnt[e];
        }
        g_off[Ee] = off;
        double mW = 0, mS = 0;
        for (int e = 0; e < Ee; e++) { mW += W[e]; mS += S[e]; }
        mW /= Ee; mS /= Ee;
        double vW = 0, vS = 0;
        for (int e = 0; e < Ee; e++) {
            vW += (W[e] - mW) * (W[e] - mW);
            vS += (S[e] - mS) * (S[e] - mS);
        }
        vW /= (Ee - 1); vS /= (Ee - 1);
        double loss = vW / (mW * mW + 1e-10) + vS / (mS * mS + 1e-10);
        if (out_size > Nn * Cc) d_out[Nn * Cc] = (float)loss;
    }
}

// ---------------- k3: scatter --------------------------------------------------
__global__ __launch_bounds__(256) void k3_scatter() {
    __shared__ int c_cnt[Ee], c_base[Ee];
    int tid = threadIdx.x;
    int n = blockIdx.x * 256 + tid;
    if (tid < Ee) c_cnt[tid] = 0;
    __syncthreads();
    int e0 = g_eidx[n * 2], e1 = g_eidx[n * 2 + 1];
    int r0 = atomicAdd(&c_cnt[e0], 1);
    int r1 = atomicAdd(&c_cnt[e1], 1);
    __syncthreads();
    if (tid < Ee) c_base[tid] = atomicAdd(&g_cur[tid], c_cnt[tid]);
    __syncthreads();
    g_list[c_base[e0] + r0] = (unsigned int)(n * 2);
    g_list[c_base[e1] + r1] = (unsigned int)(n * 2 + 1);
}

// ---------------- k4: fp16 2-term tensor-core fused MLP -----------------------
// 64 tokens per block, single W buffer, 102 KB smem -> 2 blocks/SM.
#define PADK 136
#define SM_AHI 0
#define SM_ALO 8704
#define SM_HHI 17408
#define SM_HLO 26112
#define SM_W   34816
#define K4_SMEM_BYTES ((34816 + 17408) * 2)
#define K4_GRID 1030

__device__ __forceinline__ void load_wchunk(uint32_t smbase, const __half* src,
                                            int rstride, int t0, int stride) {
    for (int i = t0; i < 2048; i += stride) {
        int r = i >> 4, u = i & 15;
        cp16(smbase + (uint32_t)(SM_W + r * PADK) * 2 + u * 16,
             src + (size_t)r * rstride + u * 8);
    }
}

__device__ __forceinline__ void gemm_stage(float (&acc)[2][4][4], uint32_t smbase,
                                           int AHI, int ALO,
                                           int wm, int wn, int a_r, int a_c,
                                           int b_r, int b_c) {
    #pragma unroll
    for (int kk = 0; kk < 8; kk++) {
        int k = kk * 16;
        uint32_t ah[2][4], al[2][4], bw[4][2];
        #pragma unroll
        for (int mi = 0; mi < 2; mi++) {
            int row = wm * 32 + mi * 16 + a_r;
            int col = k + a_c;
            ldm_x4(ah[mi][0], ah[mi][1], ah[mi][2], ah[mi][3],
                   smbase + (uint32_t)(AHI + row * PADK + col) * 2);
            ldm_x4(al[mi][0], al[mi][1], al[mi][2], al[mi][3],
                   smbase + (uint32_t)(ALO + row * PADK + col) * 2);
        }
        #pragma unroll
        for (int p = 0; p < 2; p++) {
            int row = wn * 32 + p * 16 + b_r;
            int col = k + b_c;
            uint32_t r0, r1, r2, r3;
            ldm_x4(r0, r1, r2, r3, smbase + (uint32_t)(SM_W + row * PADK + col) * 2);
            bw[2 * p][0] = r0; bw[2 * p][1] = r1; bw[2 * p + 1][0] = r2; bw[2 * p + 1][1] = r3;
        }
        #pragma unroll
        for (int mi = 0; mi < 2; mi++)
            #pragma unroll
            for (int ni = 0; ni < 4; ni++) {
                mma16816(acc[mi][ni], ah[mi], bw[ni]);
                mma16816(acc[mi][ni], al[mi], bw[ni]);
            }
    }
}

__global__ __launch_bounds__(256, 2) void k4_mlp(const float* __restrict__ fc1_b,
                                                 const float* __restrict__ fc2_b) {
    extern __shared__ __half sm[];
    __shared__ int stoks[64];
    __shared__ int s_meta[3];
    __shared__ float s_b1[128];

    int tid = threadIdx.x;
    if (tid == 0) {
        int rem = blockIdx.x;
        int e = 0, found = 0;
        for (; e < Ee; e++) {
            int t = (g_cnt[e] + 63) >> 6;
            if (rem < t) { found = 1; break; }
            rem -= t;
        }
        if (!found) s_meta[0] = -1;
        else {
            s_meta[0] = e;
            s_meta[1] = g_off[e] + rem * 64;
            int mc = g_cnt[e] - rem * 64;
            s_meta[2] = mc < 64 ? mc : 64;
        }
    }
    __syncthreads();
    int e = s_meta[0];
    if (e < 0) return;
    int base = s_meta[1], mcount = s_meta[2];

    if (tid < 64) {
        int i = tid < mcount ? tid : (mcount - 1);
        stoks[tid] = (int)g_list[base + i];
    }
    __syncthreads();

    uint32_t smbase = smem_u32(sm);

    // prologue: gather A hi/lo + W1 chunk 0
    for (int i = tid; i < 1024; i += 256) {
        int r = i >> 4, u = i & 15;
        int n = stoks[r] >> 1;
        cp16(smbase + (uint32_t)(SM_AHI + r * PADK) * 2 + u * 16, g_xf_hi + (size_t)n * 64 + u * 4);
        cp16(smbase + (uint32_t)(SM_ALO + r * PADK) * 2 + u * 16, g_xf_lo + (size_t)n * 64 + u * 4);
    }
    load_wchunk(smbase, g_w1t + (size_t)e * HFf * Cc, Cc, tid, 256);
    cp_commit();
    cp_wait0();
    __syncthreads();

    int lane = tid & 31, warp = tid >> 5;
    int wm = warp & 1, wn = warp >> 1;
    int lg = lane >> 3, lr = lane & 7;
    int a_r = lr + (lg & 1) * 8, a_c = (lg >> 1) * 8;
    int b_r = lr + (lg >> 1) * 8, b_c = (lg & 1) * 8;

    float out_acc[2][4][4];
    #pragma unroll
    for (int mi = 0; mi < 2; mi++)
        #pragma unroll
        for (int ni = 0; ni < 4; ni++)
            #pragma unroll
            for (int q = 0; q < 4; q++) out_acc[mi][ni][q] = 0.f;

    for (int hc = 0; hc < 4; hc++) {
        int hb = hc * 128;
        // ---- GEMM1 chunk (W buffer holds W1[hb:hb+128][c]) ----
        float acc[2][4][4];
        #pragma unroll
        for (int mi = 0; mi < 2; mi++)
            #pragma unroll
            for (int ni = 0; ni < 4; ni++)
                #pragma unroll
                for (int q = 0; q < 4; q++) acc[mi][ni][q] = 0.f;
        gemm_stage(acc, smbase, SM_AHI, SM_ALO, wm, wn, a_r, a_c, b_r, b_c);
        if (tid < 128) s_b1[tid] = fc1_b[e * HFf + hb + tid];
        __syncthreads();                    // W buffer free

        // start W2 chunk load into W buffer
        load_wchunk(smbase, g_w2t + (size_t)e * Cc * HFf + hb, HFf, tid, 256);
        cp_commit();

        // epilogue: bias + GELU -> H hi/lo smem (doesn't touch W)
        #pragma unroll
        for (int ni = 0; ni < 4; ni++) {
            int clocal = wn * 32 + ni * 8 + (lane & 3) * 2;
            float b0f = s_b1[clocal];
            float b1f = s_b1[clocal + 1];
            #pragma unroll
            for (int mi = 0; mi < 2; mi++) {
                int r = wm * 32 + mi * 16 + (lane >> 2);
                #pragma unroll
                for (int half = 0; half < 2; half++) {
                    int row = r + half * 8;
                    float v0 = acc[mi][ni][half * 2 + 0] + b0f;
                    float v1 = acc[mi][ni][half * 2 + 1] + b1f;
                    v0 = 0.5f * v0 * (1.f + erff(v0 * 0.7071067811865476f));
                    v1 = 0.5f * v1 * (1.f + erff(v1 * 0.7071067811865476f));
                    __half h0 = __float2half_rn(v0), h1 = __float2half_rn(v1);
                    *(uint32_t*)(&sm[SM_HHI + row * PADK + clocal]) =
                        ((uint32_t)__half_as_ushort(h1) << 16) | __half_as_ushort(h0);
                    *(uint32_t*)(&sm[SM_HLO + row * PADK + clocal]) =
                        pack_h2(v0 - __half2float(h0), v1 - __half2float(h1));
                }
            }
        }
        cp_wait0();
        __syncthreads();                    // H visible, W2 ready

        // ---- GEMM2 chunk accumulate ----
        gemm_stage(out_acc, smbase, SM_HHI, SM_HLO, wm, wn, a_r, a_c, b_r, b_c);
        __syncthreads();                    // W buffer free

        if (hc < 3) {
            load_wchunk(smbase, g_w1t + ((size_t)e * HFf + hb + 128) * Cc, Cc, tid, 256);
            cp_commit();
            cp_wait0();
            __syncthreads();
        }
    }

    // epilogue: + fc2_b, scatter rows to outbuf
    #pragma unroll
    for (int ni = 0; ni < 4; ni++) {
        int col = wn * 32 + ni * 8 + (lane & 3) * 2;
        float b0f = fc2_b[e * Cc + col];
        float b1f = fc2_b[e * Cc + col + 1];
        #pragma unroll
        for (int mi = 0; mi < 2; mi++) {
            int r = wm * 32 + mi * 16 + (lane >> 2);
            #pragma unroll
            for (int half = 0; half < 2; half++) {
                int m = r + half * 8;
                if (m < mcount) {
                    int entry = stoks[m];
                    float2 o;
                    o.x = out_acc[mi][ni][half * 2 + 0] + b0f;
                    o.y = out_acc[mi][ni][half * 2 + 1] + b1f;
                    *(float2*)(g_outbuf + (size_t)entry * Cc + col) = o;
                }
            }
        }
    }
}

// ---------------- k5: combine + transpose out ----------------------------------
__global__ __launch_bounds__(256) void k5_combine(float* __restrict__ d_out) {
    __shared__ float s[Cc * 65];
    int tid = threadIdx.x;
    int n0 = blockIdx.x * 64;
    int batch = n0 >> 14;
    int hw0 = n0 & (HW - 1);

    for (int idx = tid; idx < 64 * Cc; idx += 256) {
        int t = idx >> 7, c = idx & 127;
        int n = n0 + t;
        float o0 = g_outbuf[(size_t)(n * 2 + 0) * Cc + c];
        float o1 = g_outbuf[(size_t)(n * 2 + 1) * Cc + c];
        float g0 = g_gate[n * 2 + 0];
        float g1 = g_gate[n * 2 + 1];
        float comb = g0 * expf(o0) + g1 * expf(o1);
        if (comb == 0.f) comb = EPS_LOGF;
        s[c * 65 + t] = logf(comb);
    }
    __syncthreads();
    for (int idx = tid; idx < Cc * 64; idx += 256) {
        int c = idx >> 6, t = idx & 63;
        d_out[((size_t)(batch * Cc + c)) * HW + hw0 + t] = s[c * 65 + t];
    }
}

// ---------------- launcher ------------------------------------------------------
extern "C" void kernel_launch(void* const* d_in, const int* in_sizes, int n_in,
                              void* d_out, int out_size) {
    const float* x          = (const float*)d_in[0];
    const float* prompt     = (const float*)d_in[1];
    const float* de_cls     = (const float*)d_in[2];
    const float* w_g        = (const float*)d_in[3];
    const float* gate_boost = (const float*)d_in[4];
    const float* degra_w    = (const float*)d_in[5];
    const float* degra_b    = (const float*)d_in[6];
    const float* fc1_w      = (const float*)d_in[7];
    const float* fc1_b      = (const float*)d_in[8];
    const float* fc2_w      = (const float*)d_in[9];
    const float* fc2_b      = (const float*)d_in[10];
    float* out = (float*)d_out;

    cudaFuncSetAttribute(k4_mlp, cudaFuncAttributeMaxDynamicSharedMemorySize,
                         K4_SMEM_BYTES);

    kw1<<<Ee * 64, 256>>>(fc1_w);
    kw2<<<Ee * 64, 256>>>(fc2_w);
    k0_bias<<<1, 32>>>(prompt, de_cls, w_g, gate_boost, degra_w, degra_b);
    k1_gate<<<Nn / 64, 256>>>(x, w_g);
    k2_loss<<<1, 32>>>(out, out_size);
    k3_scatter<<<Nn / 256, 256>>>();
    k4_mlp<<<K4_GRID, 256, K4_SMEM_BYTES>>>(fc1_b, fc2_b);
    k5_combine<<<Nn / 64, 256>>>(out);
}

// round 6
// speedup vs baseline: 4.8123x; 1.0042x over previous
#include <cuda_runtime.h>
#include <cuda_fp16.h>
#include <math.h>
#include <stdint.h>

#define Bb 2
#define Cc 128
#define HW 16384
#define Nn 32768
#define Ee 6
#define HFf 512
#define EPS_LOGF 2.220446049250313e-16f

// ---------------- scratch (device globals) ------------------------------------
__device__ __align__(256) uint32_t      g_xf_hi[Nn * 64];   // packed fp16x2 [n][c/2]
__device__ __align__(256) uint32_t      g_xf_lo[Nn * 64];
__device__ float         g_gate[Nn * 2];
__device__ unsigned char g_eidx[Nn * 2];
__device__ int           g_cnt[Ee];
__device__ unsigned long long g_wsum[Ee];
__device__ int           g_off[Ee + 1];
__device__ int           g_cur[Ee];
__device__ unsigned int  g_list[Nn * 2];
__device__ float         g_outbuf[(size_t)Nn * 2 * Cc];
__device__ float         g_bias[Bb * Ee];
__device__ __align__(256) __half g_w1t[Ee * HFf * Cc];   // [e][h][c] fp16
__device__ __align__(256) __half g_w2t[Ee * Cc * HFf];   // [e][c][h] fp16

// ---------------- helpers -----------------------------------------------------
__device__ __forceinline__ uint32_t smem_u32(const void* p) {
    return (uint32_t)__cvta_generic_to_shared(p);
}
__device__ __forceinline__ void cp16(uint32_t dst, const void* src) {
    asm volatile("cp.async.cg.shared.global [%0], [%1], 16;\n" :: "r"(dst), "l"(src));
}
__device__ __forceinline__ void cp_commit() { asm volatile("cp.async.commit_group;\n"); }
__device__ __forceinline__ void cp_wait0()  { asm volatile("cp.async.wait_group 0;\n"); }

__device__ __forceinline__ void ldm_x4(uint32_t& r0, uint32_t& r1, uint32_t& r2, uint32_t& r3,
                                       uint32_t addr) {
    asm volatile("ldmatrix.sync.aligned.m8n8.x4.shared.b16 {%0,%1,%2,%3}, [%4];\n"
                 : "=r"(r0), "=r"(r1), "=r"(r2), "=r"(r3) : "r"(addr));
}
__device__ __forceinline__ void mma16816(float* c, const uint32_t* a, const uint32_t* b) {
    asm volatile(
        "mma.sync.aligned.m16n8k16.row.col.f32.f16.f16.f32 "
        "{%0,%1,%2,%3}, {%4,%5,%6,%7}, {%8,%9}, {%0,%1,%2,%3};\n"
        : "+f"(c[0]), "+f"(c[1]), "+f"(c[2]), "+f"(c[3])
        : "r"(a[0]), "r"(a[1]), "r"(a[2]), "r"(a[3]), "r"(b[0]), "r"(b[1]));
}
__device__ __forceinline__ uint32_t pack_h2(float v0, float v1) {
    __half h0 = __float2half_rn(v0), h1 = __float2half_rn(v1);
    return ((uint32_t)__half_as_ushort(h1) << 16) | __half_as_ushort(h0);
}

// ---------------- weight prep: tiled transpose fp32 -> fp16 -------------------
__global__ __launch_bounds__(256) void kw1(const float* __restrict__ fc1_w) {
    __shared__ float t[32][33];
    int bz = blockIdx.x;                       // e*64 + (h/32)*4 + (c/32)
    int e = bz >> 6, r = bz & 63;
    int hb = (r >> 2) * 32, cb = (r & 3) * 32;
    int tid = threadIdx.x;
    for (int i = tid; i < 1024; i += 256) {
        int c = i >> 5, h = i & 31;
        t[c][h] = fc1_w[((size_t)(e * Cc + cb + c)) * HFf + hb + h];
    }
    __syncthreads();
    for (int i = tid; i < 1024; i += 256) {
        int h = i >> 5, c = i & 31;
        g_w1t[((size_t)(e * HFf + hb + h)) * Cc + cb + c] = __float2half_rn(t[c][h]);
    }
}
__global__ __launch_bounds__(256) void kw2(const float* __restrict__ fc2_w) {
    __shared__ float t[32][33];
    int bz = blockIdx.x;
    int e = bz >> 6, r = bz & 63;
    int hb = (r >> 2) * 32, cb = (r & 3) * 32;
    int tid = threadIdx.x;
    for (int i = tid; i < 1024; i += 256) {
        int h = i >> 5, c = i & 31;
        t[h][c] = fc2_w[((size_t)(e * HFf + hb + h)) * Cc + cb + c];
    }
    __syncthreads();
    for (int i = tid; i < 1024; i += 256) {
        int c = i >> 5, h = i & 31;
        g_w2t[((size_t)(e * Cc + cb + c)) * HFf + hb + h] = __float2half_rn(t[h][c]);
    }
}

// ---------------- k0: per-batch gate bias + zero counters ---------------------
__global__ void k0_bias(const float* __restrict__ prompt,
                        const float* __restrict__ de_cls,
                        const float* __restrict__ w_g,
                        const float* __restrict__ gate_boost,
                        const float* __restrict__ degra_w,
                        const float* __restrict__ degra_b) {
    int tid = threadIdx.x;
    if (tid < Ee) { g_cnt[tid] = 0; g_wsum[tid] = 0ULL; }
    if (tid < Bb * Ee) {
        int b = tid / Ee, e = tid % Ee;
        float acc = 0.f;
        for (int c = 0; c < Cc; c++)
            acc += prompt[b * Cc + c] * w_g[(Cc + c) * Ee + e];
        float db = 0.f;
        for (int d = 0; d < Ee; d++)
            db += de_cls[b * Ee + d] * degra_w[d * Ee + e];
        g_bias[b * Ee + e] = acc + gate_boost[0] * (db + degra_b[e]);
    }
}

// ---------------- k1: transpose + xf fp16 hi/lo + gating ----------------------
__global__ __launch_bounds__(256) void k1_gate(const float* __restrict__ x,
                                               const float* __restrict__ w_g) {
    __shared__ float s[Cc * 65];
    __shared__ float wg_s[Cc * Ee];
    __shared__ unsigned long long s_ws[Ee];
    __shared__ int s_ct[Ee];

    int tid = threadIdx.x;
    int n0 = blockIdx.x * 64;
    int batch = n0 >> 14;
    int hw0 = n0 & (HW - 1);

    if (tid < Ee) { s_ws[tid] = 0ULL; s_ct[tid] = 0; }
    for (int i = tid; i < Cc * Ee; i += 256) wg_s[i] = w_g[i];
    for (int idx = tid; idx < Cc * 64; idx += 256) {
        int c = idx >> 6, t = idx & 63;
        s[c * 65 + t] = x[((size_t)(batch * Cc + c)) * HW + hw0 + t];
    }
    __syncthreads();

    for (int idx = tid; idx < 64 * 64; idx += 256) {
        int t = idx >> 6, c2 = idx & 63;
        int c = c2 * 2;
        float v0 = s[c * 65 + t], v1 = s[(c + 1) * 65 + t];
        __half h0 = __float2half_rn(v0), h1 = __float2half_rn(v1);
        g_xf_hi[(size_t)(n0 + t) * 64 + c2] =
            ((uint32_t)__half_as_ushort(h1) << 16) | __half_as_ushort(h0);
        g_xf_lo[(size_t)(n0 + t) * 64 + c2] =
            pack_h2(v0 - __half2float(h0), v1 - __half2float(h1));
    }

    {
        int t = tid >> 2, q = tid & 3;
        float acc[Ee];
        #pragma unroll
        for (int e = 0; e < Ee; e++) acc[e] = 0.f;
        #pragma unroll 4
        for (int cc = 0; cc < 32; cc++) {
            int c = q * 32 + cc;
            float xv = s[c * 65 + t];
            #pragma unroll
            for (int e = 0; e < Ee; e++) acc[e] += xv * wg_s[c * Ee + e];
        }
        #pragma unroll
        for (int e = 0; e < Ee; e++) {
            acc[e] += __shfl_xor_sync(0xFFFFFFFFu, acc[e], 1);
            acc[e] += __shfl_xor_sync(0xFFFFFFFFu, acc[e], 2);
        }
        if (q == 0) {
            int n = n0 + t;
            #pragma unroll
            for (int e = 0; e < Ee; e++) acc[e] += g_bias[batch * Ee + e];
            float v0 = -3.4e38f; int i0 = 0;
            #pragma unroll
            for (int e = 0; e < Ee; e++) if (acc[e] > v0) { v0 = acc[e]; i0 = e; }
            float v1 = -3.4e38f; int i1 = 0;
            #pragma unroll
            for (int e = 0; e < Ee; e++) if (e != i0 && acc[e] > v1) { v1 = acc[e]; i1 = e; }
            float tt = expf(v1 - v0);
            float inv = 1.f / (1.f + tt);
            float g0c = inv, g1c = tt * inv;
            g_eidx[n * 2 + 0] = (unsigned char)i0;
            g_eidx[n * 2 + 1] = (unsigned char)i1;
            g_gate[n * 2 + 0] = g0c;
            g_gate[n * 2 + 1] = g1c;
            atomicAdd(&s_ws[i0], (unsigned long long)llrint((double)g0c * 4294967296.0));
            atomicAdd(&s_ws[i1], (unsigned long long)llrint((double)g1c * 4294967296.0));
            atomicAdd(&s_ct[i0], 1);
            atomicAdd(&s_ct[i1], 1);
        }
    }
    __syncthreads();
    if (tid < Ee) {
        atomicAdd(&g_wsum[tid], s_ws[tid]);
        atomicAdd(&g_cnt[tid], s_ct[tid]);
    }
}

// ---------------- k2: loss + offsets ------------------------------------------
__global__ void k2_loss(float* __restrict__ d_out, int out_size) {
    if (threadIdx.x == 0) {
        int off = 0;
        double W[Ee], S[Ee];
        for (int e = 0; e < Ee; e++) {
            g_off[e] = off; g_cur[e] = off; off += g_cnt[e];
            W[e] = (double)g_wsum[e] * (1.0 / 4294967296.0);
            S[e] = (double)g_cnt[e];
        }
        g_off[Ee] = off;
        double mW = 0, mS = 0;
        for (int e = 0; e < Ee; e++) { mW += W[e]; mS += S[e]; }
        mW /= Ee; mS /= Ee;
        double vW = 0, vS = 0;
        for (int e = 0; e < Ee; e++) {
            vW += (W[e] - mW) * (W[e] - mW);
            vS += (S[e] - mS) * (S[e] - mS);
        }
        vW /= (Ee - 1); vS /= (Ee - 1);
        double loss = vW / (mW * mW + 1e-10) + vS / (mS * mS + 1e-10);
        if (out_size > Nn * Cc) d_out[Nn * Cc] = (float)loss;
    }
}

// ---------------- k3: scatter --------------------------------------------------
__global__ __launch_bounds__(256) void k3_scatter() {
    __shared__ int c_cnt[Ee], c_base[Ee];
    int tid = threadIdx.x;
    int n = blockIdx.x * 256 + tid;
    if (tid < Ee) c_cnt[tid] = 0;
    __syncthreads();
    int e0 = g_eidx[n * 2], e1 = g_eidx[n * 2 + 1];
    int r0 = atomicAdd(&c_cnt[e0], 1);
    int r1 = atomicAdd(&c_cnt[e1], 1);
    __syncthreads();
    if (tid < Ee) c_base[tid] = atomicAdd(&g_cur[tid], c_cnt[tid]);
    __syncthreads();
    g_list[c_base[e0] + r0] = (unsigned int)(n * 2);
    g_list[c_base[e1] + r1] = (unsigned int)(n * 2 + 1);
}

// ---------------- k4: fp16 2-term tensor-core fused MLP -----------------------
// 64 tokens per block, single W buffer, 102 KB smem -> 2 blocks/SM.
#define PADK 136
#define SM_AHI 0
#define SM_ALO 8704
#define SM_HHI 17408
#define SM_HLO 26112
#define SM_W   34816
#define K4_SMEM_BYTES ((34816 + 17408) * 2)
#define K4_GRID 1030

__device__ __forceinline__ void load_wchunk(uint32_t smbase, const __half* src,
                                            int rstride, int t0, int stride) {
    for (int i = t0; i < 2048; i += stride) {
        int r = i >> 4, u = i & 15;
        cp16(smbase + (uint32_t)(SM_W + r * PADK) * 2 + u * 16,
             src + (size_t)r * rstride + u * 8);
    }
}

__device__ __forceinline__ void gemm_stage(float (&acc)[2][4][4], uint32_t smbase,
                                           int AHI, int ALO,
                                           int wm, int wn, int a_r, int a_c,
                                           int b_r, int b_c) {
    #pragma unroll
    for (int kk = 0; kk < 8; kk++) {
        int k = kk * 16;
        uint32_t ah[2][4], al[2][4], bw[4][2];
        #pragma unroll
        for (int mi = 0; mi < 2; mi++) {
            int row = wm * 32 + mi * 16 + a_r;
            int col = k + a_c;
            ldm_x4(ah[mi][0], ah[mi][1], ah[mi][2], ah[mi][3],
                   smbase + (uint32_t)(AHI + row * PADK + col) * 2);
            ldm_x4(al[mi][0], al[mi][1], al[mi][2], al[mi][3],
                   smbase + (uint32_t)(ALO + row * PADK + col) * 2);
        }
        #pragma unroll
        for (int p = 0; p < 2; p++) {
            int row = wn * 32 + p * 16 + b_r;
            int col = k + b_c;
            uint32_t r0, r1, r2, r3;
            ldm_x4(r0, r1, r2, r3, smbase + (uint32_t)(SM_W + row * PADK + col) * 2);
            bw[2 * p][0] = r0; bw[2 * p][1] = r1; bw[2 * p + 1][0] = r2; bw[2 * p + 1][1] = r3;
        }
        #pragma unroll
        for (int mi = 0; mi < 2; mi++)
            #pragma unroll
            for (int ni = 0; ni < 4; ni++) {
                mma16816(acc[mi][ni], ah[mi], bw[ni]);
                mma16816(acc[mi][ni], al[mi], bw[ni]);
            }
    }
}

__global__ __launch_bounds__(256, 2) void k4_mlp(const float* __restrict__ fc1_b,
                                                 const float* __restrict__ fc2_b) {
    extern __shared__ __half sm[];
    __shared__ int stoks[64];
    __shared__ int s_meta[3];
    __shared__ float s_b1[128];

    int tid = threadIdx.x;
    if (tid == 0) {
        int rem = blockIdx.x;
        int e = 0, found = 0;
        for (; e < Ee; e++) {
            int t = (g_cnt[e] + 63) >> 6;
            if (rem < t) { found = 1; break; }
            rem -= t;
        }
        if (!found) s_meta[0] = -1;
        else {
            s_meta[0] = e;
            s_meta[1] = g_off[e] + rem * 64;
            int mc = g_cnt[e] - rem * 64;
            s_meta[2] = mc < 64 ? mc : 64;
        }
    }
    __syncthreads();
    int e = s_meta[0];
    if (e < 0) return;
    int base = s_meta[1], mcount = s_meta[2];

    if (tid < 64) {
        int i = tid < mcount ? tid : (mcount - 1);
        stoks[tid] = (int)g_list[base + i];
    }
    __syncthreads();

    uint32_t smbase = smem_u32(sm);

    // prologue: gather A hi/lo + W1 chunk 0
    for (int i = tid; i < 1024; i += 256) {
        int r = i >> 4, u = i & 15;
        int n = stoks[r] >> 1;
        cp16(smbase + (uint32_t)(SM_AHI + r * PADK) * 2 + u * 16, g_xf_hi + (size_t)n * 64 + u * 4);
        cp16(smbase + (uint32_t)(SM_ALO + r * PADK) * 2 + u * 16, g_xf_lo + (size_t)n * 64 + u * 4);
    }
    load_wchunk(smbase, g_w1t + (size_t)e * HFf * Cc, Cc, tid, 256);
    cp_commit();
    cp_wait0();
    __syncthreads();

    int lane = tid & 31, warp = tid >> 5;
    int wm = warp & 1, wn = warp >> 1;
    int lg = lane >> 3, lr = lane & 7;
    int a_r = lr + (lg & 1) * 8, a_c = (lg >> 1) * 8;
    int b_r = lr + (lg >> 1) * 8, b_c = (lg & 1) * 8;

    float out_acc[2][4][4];
    #pragma unroll
    for (int mi = 0; mi < 2; mi++)
        #pragma unroll
        for (int ni = 0; ni < 4; ni++)
            #pragma unroll
            for (int q = 0; q < 4; q++) out_acc[mi][ni][q] = 0.f;

    for (int hc = 0; hc < 4; hc++) {
        int hb = hc * 128;
        // ---- GEMM1 chunk (W buffer holds W1[hb:hb+128][c]) ----
        float acc[2][4][4];
        #pragma unroll
        for (int mi = 0; mi < 2; mi++)
            #pragma unroll
            for (int ni = 0; ni < 4; ni++)
                #pragma unroll
                for (int q = 0; q < 4; q++) acc[mi][ni][q] = 0.f;
        gemm_stage(acc, smbase, SM_AHI, SM_ALO, wm, wn, a_r, a_c, b_r, b_c);
        if (tid < 128) s_b1[tid] = fc1_b[e * HFf + hb + tid];
        __syncthreads();                    // W buffer free

        // start W2 chunk load into W buffer
        load_wchunk(smbase, g_w2t + (size_t)e * Cc * HFf + hb, HFf, tid, 256);
        cp_commit();

        // epilogue: bias + GELU -> H hi/lo smem (doesn't touch W)
        #pragma unroll
        for (int ni = 0; ni < 4; ni++) {
            int clocal = wn * 32 + ni * 8 + (lane & 3) * 2;
            float b0f = s_b1[clocal];
            float b1f = s_b1[clocal + 1];
            #pragma unroll
            for (int mi = 0; mi < 2; mi++) {
                int r = wm * 32 + mi * 16 + (lane >> 2);
                #pragma unroll
                for (int half = 0; half < 2; half++) {
                    int row = r + half * 8;
                    float v0 = acc[mi][ni][half * 2 + 0] + b0f;
                    float v1 = acc[mi][ni][half * 2 + 1] + b1f;
                    v0 = 0.5f * v0 * (1.f + erff(v0 * 0.7071067811865476f));
                    v1 = 0.5f * v1 * (1.f + erff(v1 * 0.7071067811865476f));
                    __half h0 = __float2half_rn(v0), h1 = __float2half_rn(v1);
                    *(uint32_t*)(&sm[SM_HHI + row * PADK + clocal]) =
                        ((uint32_t)__half_as_ushort(h1) << 16) | __half_as_ushort(h0);
                    *(uint32_t*)(&sm[SM_HLO + row * PADK + clocal]) =
                        pack_h2(v0 - __half2float(h0), v1 - __half2float(h1));
                }
            }
        }
        cp_wait0();
        __syncthreads();                    // H visible, W2 ready

        // ---- GEMM2 chunk accumulate ----
        gemm_stage(out_acc, smbase, SM_HHI, SM_HLO, wm, wn, a_r, a_c, b_r, b_c);
        __syncthreads();                    // W buffer free

        if (hc < 3) {
            load_wchunk(smbase, g_w1t + ((size_t)e * HFf + hb + 128) * Cc, Cc, tid, 256);
            cp_commit();
            cp_wait0();
            __syncthreads();
        }
    }

    // epilogue: + fc2_b, scatter rows to outbuf
    #pragma unroll
    for (int ni = 0; ni < 4; ni++) {
        int col = wn * 32 + ni * 8 + (lane & 3) * 2;
        float b0f = fc2_b[e * Cc + col];
        float b1f = fc2_b[e * Cc + col + 1];
        #pragma unroll
        for (int mi = 0; mi < 2; mi++) {
            int r = wm * 32 + mi * 16 + (lane >> 2);
            #pragma unroll
            for (int half = 0; half < 2; half++) {
                int m = r + half * 8;
                if (m < mcount) {
                    int entry = stoks[m];
                    float2 o;
                    o.x = out_acc[mi][ni][half * 2 + 0] + b0f;
                    o.y = out_acc[mi][ni][half * 2 + 1] + b1f;
                    *(float2*)(g_outbuf + (size_t)entry * Cc + col) = o;
                }
            }
        }
    }
}

// ---------------- k5: combine + transpose out ----------------------------------
__global__ __launch_bounds__(256) void k5_combine(float* __restrict__ d_out) {
    __shared__ float s[Cc * 65];
    int tid = threadIdx.x;
    int n0 = blockIdx.x * 64;
    int batch = n0 >> 14;
    int hw0 = n0 & (HW - 1);

    for (int idx = tid; idx < 64 * Cc; idx += 256) {
        int t = idx >> 7, c = idx & 127;
        int n = n0 + t;
        float o0 = g_outbuf[(size_t)(n * 2 + 0) * Cc + c];
        float o1 = g_outbuf[(size_t)(n * 2 + 1) * Cc + c];
        float g0 = g_gate[n * 2 + 0];
        float g1 = g_gate[n * 2 + 1];
        float comb = g0 * expf(o0) + g1 * expf(o1);
        if (comb == 0.f) comb = EPS_LOGF;
        s[c * 65 + t] = logf(comb);
    }
    __syncthreads();
    for (int idx = tid; idx < Cc * 64; idx += 256) {
        int c = idx >> 6, t = idx & 63;
        d_out[((size_t)(batch * Cc + c)) * HW + hw0 + t] = s[c * 65 + t];
    }
}

// ---------------- launcher ------------------------------------------------------
extern "C" void kernel_launch(void* const* d_in, const int* in_sizes, int n_in,
                              void* d_out, int out_size) {
    const float* x          = (const float*)d_in[0];
    const float* prompt     = (const float*)d_in[1];
    const float* de_cls     = (const float*)d_in[2];
    const float* w_g        = (const float*)d_in[3];
    const float* gate_boost = (const float*)d_in[4];
    const float* degra_w    = (const float*)d_in[5];
    const float* degra_b    = (const float*)d_in[6];
    const float* fc1_w      = (const float*)d_in[7];
    const float* fc1_b      = (const float*)d_in[8];
    const float* fc2_w      = (const float*)d_in[9];
    const float* fc2_b      = (const float*)d_in[10];
    float* out = (float*)d_out;

    cudaFuncSetAttribute(k4_mlp, cudaFuncAttributeMaxDynamicSharedMemorySize,
                         K4_SMEM_BYTES);

    kw1<<<Ee * 64, 256>>>(fc1_w);
    kw2<<<Ee * 64, 256>>>(fc2_w);
    k0_bias<<<1, 32>>>(prompt, de_cls, w_g, gate_boost, degra_w, degra_b);
    k1_gate<<<Nn / 64, 256>>>(x, w_g);
    k2_loss<<<1, 32>>>(out, out_size);
    k3_scatter<<<Nn / 256, 256>>>();
    k4_mlp<<<K4_GRID, 256, K4_SMEM_BYTES>>>(fc1_b, fc2_b);
    k5_combine<<<Nn / 64, 256>>>(out);
}